// round 1
// baseline (speedup 1.0000x reference)
#include <cuda_runtime.h>
#include <math.h>

#define BB 8
#define NN 1024
#define DD 512
#define HH 8
#define HD 64
#define MTOK (BB*NN)   // 8192

// Scratch (device globals: no allocation allowed)
__device__ float g_qT[BB*HH*HD*NN];   // [B,H,d,n]  16MB
__device__ float g_kT[BB*HH*HD*NN];   // [B,H,d,n]  16MB
__device__ float g_v [BB*HH*NN*HD];   // [B,H,n,d]  16MB
__device__ float g_y [MTOK*DD];       // [token, D] 16MB

// ---------------------------------------------------------------------------
// K1: QKV GEMM  (x[8192,512] @ W[512,1536] + b) -> split into g_qT/g_kT/g_v
// tiles: BM=128, BN=64, BK=16; 256 threads; 8x4 micro-tile per thread
// ---------------------------------------------------------------------------
__global__ __launch_bounds__(256) void hp_qkv_gemm(
    const float* __restrict__ x, const float* __restrict__ W,
    const float* __restrict__ bqkv)
{
    __shared__ float As[16*128];
    __shared__ float Bs[16*64];
    const int tid = threadIdx.x;
    const int tr = tid >> 4;      // 0..15
    const int tc = tid & 15;      // 0..15
    const int bm = blockIdx.y * 128;
    const int bn = blockIdx.x * 64;

    float acc[8][4];
#pragma unroll
    for (int i = 0; i < 8; ++i)
#pragma unroll
        for (int j = 0; j < 4; ++j) acc[i][j] = 0.f;

    for (int k0 = 0; k0 < 512; k0 += 16) {
#pragma unroll
        for (int it = 0; it < 2; ++it) {
            int v  = tid + it * 256;        // 0..511
            int m  = v >> 2;                // 0..127
            int kq = (v & 3) << 2;          // 0,4,8,12
            float4 t4 = *(const float4*)&x[(size_t)(bm + m) * 512 + k0 + kq];
            As[(kq + 0) * 128 + m] = t4.x;
            As[(kq + 1) * 128 + m] = t4.y;
            As[(kq + 2) * 128 + m] = t4.z;
            As[(kq + 3) * 128 + m] = t4.w;
        }
        {
            int kk = tid >> 4;              // 0..15
            int c4 = (tid & 15) << 2;       // 0..60
            *(float4*)&Bs[kk * 64 + c4] =
                *(const float4*)&W[(size_t)(k0 + kk) * 1536 + bn + c4];
        }
        __syncthreads();
#pragma unroll
        for (int kk = 0; kk < 16; ++kk) {
            float4 a0 = *(float4*)&As[kk * 128 + tr * 8];
            float4 a1 = *(float4*)&As[kk * 128 + tr * 8 + 4];
            float4 b0 = *(float4*)&Bs[kk * 64 + tc * 4];
            float av[8] = {a0.x, a0.y, a0.z, a0.w, a1.x, a1.y, a1.z, a1.w};
            float bv[4] = {b0.x, b0.y, b0.z, b0.w};
#pragma unroll
            for (int i = 0; i < 8; ++i)
#pragma unroll
                for (int j = 0; j < 4; ++j)
                    acc[i][j] = fmaf(av[i], bv[j], acc[i][j]);
        }
        __syncthreads();
    }

#pragma unroll
    for (int i = 0; i < 8; ++i) {
        int m  = bm + tr * 8 + i;
        int bi = m >> 10;            // batch
        int n  = m & 1023;           // token within batch
#pragma unroll
        for (int j = 0; j < 4; ++j) {
            int c = bn + tc * 4 + j;
            float val = acc[i][j] + bqkv[c];
            int h     = c / 192;
            int rem   = c - h * 192;
            int which = rem >> 6;    // 0=q 1=k 2=v
            int t     = rem & 63;
            if (which == 0)
                g_qT[(((size_t)bi * HH + h) * HD + t) * NN + n] = val;
            else if (which == 1)
                g_kT[(((size_t)bi * HH + h) * HD + t) * NN + n] = val;
            else
                g_v [(((size_t)bi * HH + h) * NN + n) * HD + t] = val;
        }
    }
}

// ---------------------------------------------------------------------------
// K2: flash attention, fp32, per (b, h, 64-query tile). 256 threads.
// S-tile 64x64 per iteration; online softmax over K=1024; bias added pre-max.
// Smem: Qst[d][q] 16KB + KSS 16KB (K-tile [d][k], then aliased as S/P) +
// Vs[k][t] 16KB = 48KB exactly. scale/l broadcast via intra-warp shfl.
// ---------------------------------------------------------------------------
__global__ __launch_bounds__(256) void hp_attn(const float* __restrict__ bias)
{
    __shared__ float Qst[64 * 64];
    __shared__ float KSS[64 * 64];
    __shared__ float Vs [64 * 64];

    const int tid = threadIdx.x;
    const int tr  = tid >> 4;     // 0..15 (q micro-row group)
    const int tc  = tid & 15;     // 0..15 (k / t micro-col group)
    const int h   = blockIdx.x;
    const int qt  = blockIdx.y;
    const int b   = blockIdx.z;
    const int bh  = b * HH + h;
    const int q0  = qt * 64;

    // load Q tile transposed [d][q], pre-scaled by 1/sqrt(64)
    const float* qbase = g_qT + ((size_t)bh * HD) * NN + q0;
    for (int idx = tid; idx < 4096; idx += 256) {
        int d  = idx >> 6;
        int qq = idx & 63;
        Qst[idx] = qbase[(size_t)d * NN + qq] * 0.125f;
    }

    float o[4][4];
#pragma unroll
    for (int i = 0; i < 4; ++i)
#pragma unroll
        for (int j = 0; j < 4; ++j) o[i][j] = 0.f;

    float mrow = -1e30f, lrow = 0.f;   // softmax state for row (tid>>2)
    const int myrow = tid >> 2;        // 0..63
    const int part  = tid & 3;         // 0..3 (16 keys each)

    const float* kbase = g_kT + ((size_t)bh * HD) * NN;
    const float* vbase = g_v  + ((size_t)bh * NN) * HD;
    const float* bbase = bias + (((size_t)b * NN + q0) * NN) * HH + h;

    for (int kt = 0; kt < 16; ++kt) {
        __syncthreads();   // previous phase-2 done (also covers Qst first load)
        const int k0 = kt * 64;
        for (int idx = tid; idx < 4096; idx += 256) {
            int d  = idx >> 6;
            int kk = idx & 63;
            KSS[idx] = kbase[(size_t)d * NN + k0 + kk];   // K-tile [d][k]
        }
        for (int idx = tid; idx < 4096; idx += 256) {
            int kk = idx >> 6;
            int t  = idx & 63;
            Vs[idx] = vbase[(size_t)(k0 + kk) * HD + t];  // V-tile [k][t]
        }
        __syncthreads();

        // phase 1: S = Q K^T (+bias), 4x4 micro per thread
        float s[4][4];
#pragma unroll
        for (int i = 0; i < 4; ++i)
#pragma unroll
            for (int j = 0; j < 4; ++j) s[i][j] = 0.f;
#pragma unroll
        for (int d = 0; d < 64; ++d) {
            float4 a  = *(float4*)&Qst[d * 64 + tr * 4];
            float4 bb = *(float4*)&KSS[d * 64 + tc * 4];
            float av[4] = {a.x, a.y, a.z, a.w};
            float bv[4] = {bb.x, bb.y, bb.z, bb.w};
#pragma unroll
            for (int i = 0; i < 4; ++i)
#pragma unroll
                for (int j = 0; j < 4; ++j)
                    s[i][j] = fmaf(av[i], bv[j], s[i][j]);
        }
#pragma unroll
        for (int i = 0; i < 4; ++i)
#pragma unroll
            for (int j = 0; j < 4; ++j)
                s[i][j] += __ldg(&bbase[((size_t)(tr * 4 + i) * NN +
                                         (k0 + tc * 4 + j)) * HH]);
        __syncthreads();   // all done reading KSS as K-tile

        // write S[q][k] into the aliased buffer
#pragma unroll
        for (int i = 0; i < 4; ++i)
#pragma unroll
            for (int j = 0; j < 4; ++j)
                KSS[(tr * 4 + i) * 64 + tc * 4 + j] = s[i][j];
        __syncthreads();

        // online softmax on row `myrow`, 16 keys per `part`
        float p[16];
        float lm = -1e30f;
#pragma unroll
        for (int u = 0; u < 16; ++u) {
            p[u] = KSS[myrow * 64 + part * 16 + u];
            lm = fmaxf(lm, p[u]);
        }
        lm = fmaxf(lm, __shfl_xor_sync(0xffffffffu, lm, 1));
        lm = fmaxf(lm, __shfl_xor_sync(0xffffffffu, lm, 2));
        float mnew  = fmaxf(mrow, lm);
        float scale = __expf(mrow - mnew);
        float sum   = 0.f;
#pragma unroll
        for (int u = 0; u < 16; ++u) {
            p[u] = __expf(p[u] - mnew);
            sum += p[u];
        }
        sum += __shfl_xor_sync(0xffffffffu, sum, 1);
        sum += __shfl_xor_sync(0xffffffffu, sum, 2);
        lrow = lrow * scale + sum;
        mrow = mnew;
        __syncthreads();   // everyone done reading S rows

        // write P transposed: KSS[k][q]
#pragma unroll
        for (int u = 0; u < 16; ++u)
            KSS[(part * 16 + u) * 64 + myrow] = p[u];
        __syncthreads();

        // rescale O by this tile's scale (fetched intra-warp) then O += P V
#pragma unroll
        for (int i = 0; i < 4; ++i) {
            int src = ((tr & 1) << 4) + i * 4;  // lane holding row tr*4+i
            float sc = __shfl_sync(0xffffffffu, scale, src);
#pragma unroll
            for (int j = 0; j < 4; ++j) o[i][j] *= sc;
        }
#pragma unroll
        for (int kk = 0; kk < 64; ++kk) {
            float4 a  = *(float4*)&KSS[kk * 64 + tr * 4];
            float4 bb = *(float4*)&Vs[kk * 64 + tc * 4];
            float av[4] = {a.x, a.y, a.z, a.w};
            float bv[4] = {bb.x, bb.y, bb.z, bb.w};
#pragma unroll
            for (int i = 0; i < 4; ++i)
#pragma unroll
                for (int j = 0; j < 4; ++j)
                    o[i][j] = fmaf(av[i], bv[j], o[i][j]);
        }
    }

    // finalize: divide by l, write y[token, h*64+t]
#pragma unroll
    for (int i = 0; i < 4; ++i) {
        int src = ((tr & 1) << 4) + i * 4;
        float lv  = __shfl_sync(0xffffffffu, lrow, src);
        float inv = 1.f / lv;
        int q = q0 + tr * 4 + i;
#pragma unroll
        for (int j = 0; j < 4; ++j)
            g_y[((size_t)b * NN + q) * DD + h * HD + tc * 4 + j] = o[i][j] * inv;
    }
}

// ---------------------------------------------------------------------------
// K3: output GEMM  out = g_y[8192,512] @ W_o[512,512] + b_o
// ---------------------------------------------------------------------------
__global__ __launch_bounds__(256) void hp_out_gemm(
    const float* __restrict__ Wo, const float* __restrict__ bo,
    float* __restrict__ out)
{
    __shared__ float As[16*128];
    __shared__ float Bs[16*64];
    const int tid = threadIdx.x;
    const int tr = tid >> 4;
    const int tc = tid & 15;
    const int bm = blockIdx.y * 128;
    const int bn = blockIdx.x * 64;

    float acc[8][4];
#pragma unroll
    for (int i = 0; i < 8; ++i)
#pragma unroll
        for (int j = 0; j < 4; ++j) acc[i][j] = 0.f;

    for (int k0 = 0; k0 < 512; k0 += 16) {
#pragma unroll
        for (int it = 0; it < 2; ++it) {
            int v  = tid + it * 256;
            int m  = v >> 2;
            int kq = (v & 3) << 2;
            float4 t4 = *(const float4*)&g_y[(size_t)(bm + m) * 512 + k0 + kq];
            As[(kq + 0) * 128 + m] = t4.x;
            As[(kq + 1) * 128 + m] = t4.y;
            As[(kq + 2) * 128 + m] = t4.z;
            As[(kq + 3) * 128 + m] = t4.w;
        }
        {
            int kk = tid >> 4;
            int c4 = (tid & 15) << 2;
            *(float4*)&Bs[kk * 64 + c4] =
                *(const float4*)&Wo[(size_t)(k0 + kk) * 512 + bn + c4];
        }
        __syncthreads();
#pragma unroll
        for (int kk = 0; kk < 16; ++kk) {
            float4 a0 = *(float4*)&As[kk * 128 + tr * 8];
            float4 a1 = *(float4*)&As[kk * 128 + tr * 8 + 4];
            float4 b0 = *(float4*)&Bs[kk * 64 + tc * 4];
            float av[8] = {a0.x, a0.y, a0.z, a0.w, a1.x, a1.y, a1.z, a1.w};
            float bv[4] = {b0.x, b0.y, b0.z, b0.w};
#pragma unroll
            for (int i = 0; i < 8; ++i)
#pragma unroll
                for (int j = 0; j < 4; ++j)
                    acc[i][j] = fmaf(av[i], bv[j], acc[i][j]);
        }
        __syncthreads();
    }

#pragma unroll
    for (int i = 0; i < 8; ++i) {
        int m = bm + tr * 8 + i;
#pragma unroll
        for (int j = 0; j < 4; ++j) {
            int c = bn + tc * 4 + j;
            out[(size_t)m * 512 + c] = acc[i][j] + bo[c];
        }
    }
}

// ---------------------------------------------------------------------------
extern "C" void kernel_launch(void* const* d_in, const int* in_sizes, int n_in,
                              void* d_out, int out_size)
{
    const float* x    = (const float*)d_in[0];
    const float* bias = (const float*)d_in[1];
    const float* Wqkv = (const float*)d_in[2];
    const float* bqkv = (const float*)d_in[3];
    const float* Wo   = (const float*)d_in[4];
    const float* bo   = (const float*)d_in[5];
    float* out = (float*)d_out;

    hp_qkv_gemm<<<dim3(1536 / 64, 8192 / 128), 256>>>(x, Wqkv, bqkv);
    // h fastest so the 8 heads sharing each 32B bias sector are L2-co-resident
    hp_attn<<<dim3(HH, NN / 64, BB), 256>>>(bias);
    hp_out_gemm<<<dim3(512 / 64, 8192 / 128), 256>>>(Wo, bo, out);
}

// round 2
// speedup vs baseline: 2.7580x; 2.7580x over previous
#include <cuda_runtime.h>
#include <math.h>
#include <stdint.h>

#define BB 8
#define NN 1024
#define DD 512
#define HH 8
#define HD 64

// Scratch (device globals: no allocation allowed)
__device__ float g_qT[BB*HH*HD*NN];    // [B,H,d,n]   16MB
__device__ float g_kT[BB*HH*HD*NN];    // [B,H,d,n]   16MB
__device__ float g_v [BB*HH*NN*HD];    // [B,H,n,d]   16MB
__device__ float g_y [BB*NN*DD];       // [token, D]  16MB
__device__ float g_biasT[(size_t)BB*HH*NN*NN];  // [B,H,q,k] 268MB

__device__ __forceinline__ float cvt_tf32(float x) {
    uint32_t u;
    asm("cvt.rna.tf32.f32 %0, %1;" : "=r"(u) : "f"(x));
    return __uint_as_float(u);
}

#define MMA16N8K8(d, a0, a1, a2, a3, b0, b1)                              \
    asm volatile("mma.sync.aligned.m16n8k8.row.col.f32.tf32.tf32.f32 "    \
                 "{%0,%1,%2,%3},{%4,%5,%6,%7},{%8,%9},{%0,%1,%2,%3};"     \
                 : "+f"(d[0]), "+f"(d[1]), "+f"(d[2]), "+f"(d[3])         \
                 : "r"(a0), "r"(a1), "r"(a2), "r"(a3), "r"(b0), "r"(b1))

// ---------------------------------------------------------------------------
// K0: bias transpose  [B][q][k][H] -> g_biasT [B][H][q*k]
// Each thread owns one qk index: reads 8 contiguous floats (all h), writes 8
// scalars into 8 coalesced rows.
// ---------------------------------------------------------------------------
__global__ __launch_bounds__(256) void hp_bias_T(const float* __restrict__ bias)
{
    const size_t qk = (size_t)blockIdx.x * 256 + threadIdx.x;
    const int b = blockIdx.y;
    const float4* p = (const float4*)(bias + ((size_t)b * 1048576 + qk) * 8);
    float4 t0 = p[0];
    float4 t1 = p[1];
    float* o = g_biasT + (size_t)b * 8388608 + qk;
    o[0 * 1048576] = t0.x;
    o[1 * 1048576] = t0.y;
    o[2 * 1048576] = t0.z;
    o[3 * 1048576] = t0.w;
    o[4 * 1048576] = t1.x;
    o[5 * 1048576] = t1.y;
    o[6 * 1048576] = t1.z;
    o[7 * 1048576] = t1.w;
}

// ---------------------------------------------------------------------------
// K1/K3: tf32 HMMA GEMM, BM=128, BN=128, BK=32, 8 warps (4x2), warp 32x64.
// SPLIT=true: C = x @ W_qkv + b, scattered into g_qT/g_kT/g_v.
// SPLIT=false: C = g_y @ W_o + b_o -> outp row-major.
// ---------------------------------------------------------------------------
template<int LDN, bool SPLIT>
__global__ __launch_bounds__(256) void hp_gemm_mma(
    const float* __restrict__ Ain, const float* __restrict__ Wm,
    const float* __restrict__ bv, float* __restrict__ outp)
{
    __shared__ float As[128][36];   // [m][k]  (A-pattern, stride 36)
    __shared__ float Bs[32][136];   // [k][n]  (B-pattern, stride 136)

    const float* A = SPLIT ? Ain : g_y;
    const int tid  = threadIdx.x;
    const int warp = tid >> 5, lane = tid & 31;
    const int grp  = lane >> 2, tg = lane & 3;
    const int wm   = warp >> 1, wn = warp & 1;
    const int bm   = blockIdx.y * 128, bn = blockIdx.x * 128;

    float acc[2][8][4];
#pragma unroll
    for (int i = 0; i < 2; ++i)
#pragma unroll
        for (int j = 0; j < 8; ++j)
#pragma unroll
            for (int r = 0; r < 4; ++r) acc[i][j][r] = 0.f;

    for (int k0 = 0; k0 < 512; k0 += 32) {
#pragma unroll
        for (int i = 0; i < 4; ++i) {
            int v = i * 256 + tid;
            int r = v >> 3, c4 = (v & 7) << 2;
            float4 t = *(const float4*)&A[(size_t)(bm + r) * 512 + k0 + c4];
            t.x = cvt_tf32(t.x); t.y = cvt_tf32(t.y);
            t.z = cvt_tf32(t.z); t.w = cvt_tf32(t.w);
            *(float4*)&As[r][c4] = t;
        }
#pragma unroll
        for (int i = 0; i < 4; ++i) {
            int v = i * 256 + tid;
            int r = v >> 5, c4 = (v & 31) << 2;
            float4 t = *(const float4*)&Wm[(size_t)(k0 + r) * LDN + bn + c4];
            t.x = cvt_tf32(t.x); t.y = cvt_tf32(t.y);
            t.z = cvt_tf32(t.z); t.w = cvt_tf32(t.w);
            *(float4*)&Bs[r][c4] = t;
        }
        __syncthreads();
#pragma unroll
        for (int ks = 0; ks < 4; ++ks) {
            const int kb = ks * 8;
            uint32_t a[2][4];
#pragma unroll
            for (int mf = 0; mf < 2; ++mf) {
                int r = wm * 32 + mf * 16 + grp;
                a[mf][0] = __float_as_uint(As[r][kb + tg]);
                a[mf][1] = __float_as_uint(As[r + 8][kb + tg]);
                a[mf][2] = __float_as_uint(As[r][kb + tg + 4]);
                a[mf][3] = __float_as_uint(As[r + 8][kb + tg + 4]);
            }
#pragma unroll
            for (int nf = 0; nf < 8; ++nf) {
                int c = wn * 64 + nf * 8 + grp;
                uint32_t b0 = __float_as_uint(Bs[kb + tg][c]);
                uint32_t b1 = __float_as_uint(Bs[kb + tg + 4][c]);
                MMA16N8K8(acc[0][nf], a[0][0], a[0][1], a[0][2], a[0][3], b0, b1);
                MMA16N8K8(acc[1][nf], a[1][0], a[1][1], a[1][2], a[1][3], b0, b1);
            }
        }
        __syncthreads();
    }

#pragma unroll
    for (int mf = 0; mf < 2; ++mf) {
#pragma unroll
        for (int rr = 0; rr < 2; ++rr) {
            const int m = bm + wm * 32 + mf * 16 + grp + rr * 8;
#pragma unroll
            for (int nf = 0; nf < 8; ++nf) {
                const int c = bn + wn * 64 + nf * 8 + tg * 2;
                float v0 = acc[mf][nf][rr * 2]     + bv[c];
                float v1 = acc[mf][nf][rr * 2 + 1] + bv[c + 1];
                if (SPLIT) {
                    int bi = m >> 10, n = m & 1023;
                    int h = c / 192, rem = c - h * 192;
                    int which = rem >> 6, t = rem & 63;
                    if (which == 0) {
                        g_qT[(((size_t)bi * 8 + h) * 64 + t)     * 1024 + n] = v0;
                        g_qT[(((size_t)bi * 8 + h) * 64 + t + 1) * 1024 + n] = v1;
                    } else if (which == 1) {
                        g_kT[(((size_t)bi * 8 + h) * 64 + t)     * 1024 + n] = v0;
                        g_kT[(((size_t)bi * 8 + h) * 64 + t + 1) * 1024 + n] = v1;
                    } else {
                        float2 w2 = make_float2(v0, v1);
                        *(float2*)&g_v[(((size_t)bi * 8 + h) * 1024 + n) * 64 + t] = w2;
                    }
                } else {
                    float2 w2 = make_float2(v0, v1);
                    *(float2*)&outp[(size_t)m * 512 + c] = w2;
                }
            }
        }
    }
}

// ---------------------------------------------------------------------------
// K2: flash attention, tf32 HMMA. Block = (h, 128-q-tile, b), 256 thr, 8 warps.
// Each warp owns 16 q rows. K-tiles of 32 keys, 32 iterations over N=1024.
// Q frags live in registers; online softmax in c-frag layout (no shuffles for
// O rescale); P routed via smem (warp-private rows).
// ---------------------------------------------------------------------------
__global__ __launch_bounds__(256) void hp_attn_mma()
{
    __shared__ float Ks[64][40];    // [d][key]  B-pattern, stride 40
    __shared__ float Vs[32][72];    // [key][d]  B-pattern, stride 72
    __shared__ float Ps[128][36];   // [q][key]  A-pattern, stride 36

    const int tid  = threadIdx.x;
    const int warp = tid >> 5, lane = tid & 31;
    const int grp  = lane >> 2, tg = lane & 3;
    const int h  = blockIdx.x;
    const int qt = blockIdx.y;
    const int b  = blockIdx.z;
    const int bh = b * HH + h;
    const int q0 = qt * 128;

    // Q fragments in registers, pre-scaled by 1/sqrt(64)
    const float* qbase = g_qT + (size_t)bh * HD * NN;
    const int qr = q0 + warp * 16 + grp;
    uint32_t qa[8][4];
#pragma unroll
    for (int s = 0; s < 8; ++s) {
        int d0 = s * 8 + tg;
        qa[s][0] = __float_as_uint(cvt_tf32(qbase[(size_t)d0       * NN + qr]     * 0.125f));
        qa[s][1] = __float_as_uint(cvt_tf32(qbase[(size_t)d0       * NN + qr + 8] * 0.125f));
        qa[s][2] = __float_as_uint(cvt_tf32(qbase[(size_t)(d0 + 4) * NN + qr]     * 0.125f));
        qa[s][3] = __float_as_uint(cvt_tf32(qbase[(size_t)(d0 + 4) * NN + qr + 8] * 0.125f));
    }

    float o[8][4];
#pragma unroll
    for (int i = 0; i < 8; ++i)
#pragma unroll
        for (int j = 0; j < 4; ++j) o[i][j] = 0.f;
    float m0 = -1e30f, m1 = -1e30f, l0 = 0.f, l1 = 0.f;

    const float* kb = g_kT + (size_t)bh * HD * NN;
    const float* vb = g_v  + (size_t)bh * NN * HD;
    const float* br0 = g_biasT + ((size_t)bh << 20) + (size_t)(q0 + warp * 16 + grp) * 1024;
    const float* br1 = br0 + 8 * 1024;

    for (int kt = 0; kt < 32; ++kt) {
        const int k0 = kt * 32;
        __syncthreads();
#pragma unroll
        for (int i = 0; i < 2; ++i) {           // Ks: 64 x 32
            int v = i * 256 + tid;
            int d = v >> 3, c4 = (v & 7) << 2;
            float4 t = *(const float4*)&kb[(size_t)d * NN + k0 + c4];
            t.x = cvt_tf32(t.x); t.y = cvt_tf32(t.y);
            t.z = cvt_tf32(t.z); t.w = cvt_tf32(t.w);
            *(float4*)&Ks[d][c4] = t;
        }
#pragma unroll
        for (int i = 0; i < 2; ++i) {           // Vs: 32 x 64
            int v = i * 256 + tid;
            int r = v >> 4, c4 = (v & 15) << 2;
            float4 t = *(const float4*)&vb[(size_t)(k0 + r) * HD + c4];
            t.x = cvt_tf32(t.x); t.y = cvt_tf32(t.y);
            t.z = cvt_tf32(t.z); t.w = cvt_tf32(t.w);
            *(float4*)&Vs[r][c4] = t;
        }
        __syncthreads();

        // S = Q K^T  (4 n-frags of 8 keys, 8 k-steps over d)
        float s_[4][4];
#pragma unroll
        for (int nf = 0; nf < 4; ++nf)
#pragma unroll
            for (int r = 0; r < 4; ++r) s_[nf][r] = 0.f;
#pragma unroll
        for (int ks = 0; ks < 8; ++ks) {
#pragma unroll
            for (int nf = 0; nf < 4; ++nf) {
                int key = nf * 8 + grp;
                uint32_t b0 = __float_as_uint(Ks[ks * 8 + tg][key]);
                uint32_t b1 = __float_as_uint(Ks[ks * 8 + tg + 4][key]);
                MMA16N8K8(s_[nf], qa[ks][0], qa[ks][1], qa[ks][2], qa[ks][3], b0, b1);
            }
        }
        // bias add (coalesced float2 from transposed bias)
#pragma unroll
        for (int nf = 0; nf < 4; ++nf) {
            int kc = k0 + nf * 8 + tg * 2;
            float2 t0 = *(const float2*)(br0 + kc);
            float2 t1 = *(const float2*)(br1 + kc);
            s_[nf][0] += t0.x; s_[nf][1] += t0.y;
            s_[nf][2] += t1.x; s_[nf][3] += t1.y;
        }

        // online softmax (rows grp / grp+8 of this warp)
        float mx0 = -1e30f, mx1 = -1e30f;
#pragma unroll
        for (int nf = 0; nf < 4; ++nf) {
            mx0 = fmaxf(mx0, fmaxf(s_[nf][0], s_[nf][1]));
            mx1 = fmaxf(mx1, fmaxf(s_[nf][2], s_[nf][3]));
        }
        mx0 = fmaxf(mx0, __shfl_xor_sync(0xffffffffu, mx0, 1));
        mx0 = fmaxf(mx0, __shfl_xor_sync(0xffffffffu, mx0, 2));
        mx1 = fmaxf(mx1, __shfl_xor_sync(0xffffffffu, mx1, 1));
        mx1 = fmaxf(mx1, __shfl_xor_sync(0xffffffffu, mx1, 2));
        float mn0 = fmaxf(m0, mx0), mn1 = fmaxf(m1, mx1);
        float sc0 = __expf(m0 - mn0), sc1 = __expf(m1 - mn1);
        float sum0 = 0.f, sum1 = 0.f;
#pragma unroll
        for (int nf = 0; nf < 4; ++nf) {
            s_[nf][0] = __expf(s_[nf][0] - mn0);
            s_[nf][1] = __expf(s_[nf][1] - mn0);
            s_[nf][2] = __expf(s_[nf][2] - mn1);
            s_[nf][3] = __expf(s_[nf][3] - mn1);
            sum0 += s_[nf][0] + s_[nf][1];
            sum1 += s_[nf][2] + s_[nf][3];
        }
        sum0 += __shfl_xor_sync(0xffffffffu, sum0, 1);
        sum0 += __shfl_xor_sync(0xffffffffu, sum0, 2);
        sum1 += __shfl_xor_sync(0xffffffffu, sum1, 1);
        sum1 += __shfl_xor_sync(0xffffffffu, sum1, 2);
        l0 = l0 * sc0 + sum0;
        l1 = l1 * sc1 + sum1;
        m0 = mn0; m1 = mn1;

        // rescale O (same c-frag row ownership as S: no shuffles)
#pragma unroll
        for (int nf = 0; nf < 8; ++nf) {
            o[nf][0] *= sc0; o[nf][1] *= sc0;
            o[nf][2] *= sc1; o[nf][3] *= sc1;
        }

        // P -> smem (warp-private rows), tf32
        {
            int r0 = warp * 16 + grp;
#pragma unroll
            for (int nf = 0; nf < 4; ++nf) {
                int c = nf * 8 + tg * 2;
                float2 p0 = make_float2(cvt_tf32(s_[nf][0]), cvt_tf32(s_[nf][1]));
                float2 p1 = make_float2(cvt_tf32(s_[nf][2]), cvt_tf32(s_[nf][3]));
                *(float2*)&Ps[r0][c]     = p0;
                *(float2*)&Ps[r0 + 8][c] = p1;
            }
        }
        __syncwarp();

        // O += P V  (reduction over 32 keys = 4 k-steps; 8 n-frags over d)
#pragma unroll
        for (int ks = 0; ks < 4; ++ks) {
            int r0 = warp * 16 + grp;
            uint32_t a0 = __float_as_uint(Ps[r0][ks * 8 + tg]);
            uint32_t a1 = __float_as_uint(Ps[r0 + 8][ks * 8 + tg]);
            uint32_t a2 = __float_as_uint(Ps[r0][ks * 8 + tg + 4]);
            uint32_t a3 = __float_as_uint(Ps[r0 + 8][ks * 8 + tg + 4]);
#pragma unroll
            for (int nf = 0; nf < 8; ++nf) {
                int dc = nf * 8 + grp;
                uint32_t b0 = __float_as_uint(Vs[ks * 8 + tg][dc]);
                uint32_t b1 = __float_as_uint(Vs[ks * 8 + tg + 4][dc]);
                MMA16N8K8(o[nf], a0, a1, a2, a3, b0, b1);
            }
        }
    }

    // epilogue: O /= l, write g_y[token][h*64 + d]
    const float inv0 = 1.f / l0, inv1 = 1.f / l1;
    const size_t row0 = (size_t)b * NN + q0 + warp * 16 + grp;
    const size_t row1 = row0 + 8;
#pragma unroll
    for (int nf = 0; nf < 8; ++nf) {
        int c = h * 64 + nf * 8 + tg * 2;
        float2 w0 = make_float2(o[nf][0] * inv0, o[nf][1] * inv0);
        float2 w1 = make_float2(o[nf][2] * inv1, o[nf][3] * inv1);
        *(float2*)&g_y[row0 * DD + c] = w0;
        *(float2*)&g_y[row1 * DD + c] = w1;
    }
}

// ---------------------------------------------------------------------------
extern "C" void kernel_launch(void* const* d_in, const int* in_sizes, int n_in,
                              void* d_out, int out_size)
{
    const float* x    = (const float*)d_in[0];
    const float* bias = (const float*)d_in[1];
    const float* Wqkv = (const float*)d_in[2];
    const float* bqkv = (const float*)d_in[3];
    const float* Wo   = (const float*)d_in[4];
    const float* bo   = (const float*)d_in[5];
    float* out = (float*)d_out;

    hp_bias_T<<<dim3(4096, 8), 256>>>(bias);
    hp_gemm_mma<1536, true ><<<dim3(12, 64), 256>>>(x, Wqkv, bqkv, nullptr);
    hp_attn_mma<<<dim3(HH, NN / 128, BB), 256>>>();
    hp_gemm_mma<512, false><<<dim3(4, 64), 256>>>(nullptr, Wo, bo, out);
}

// round 3
// speedup vs baseline: 2.9849x; 1.0823x over previous
#include <cuda_runtime.h>
#include <math.h>
#include <stdint.h>

#define BB 8
#define NN 1024
#define DD 512
#define HH 8
#define HD 64

__device__ float g_qT[BB*HH*HD*NN];    // [B,H,d,n]   16MB
__device__ float g_kT[BB*HH*HD*NN];    // [B,H,d,n]   16MB
__device__ float g_v [BB*HH*NN*HD];    // [B,H,n,d]   16MB
__device__ float g_y [BB*NN*DD];       // [token, D]  16MB
__device__ float g_biasT[(size_t)BB*HH*NN*NN];  // [B,H,q,k] 268MB

__device__ __forceinline__ float cvt_tf32(float x) {
    uint32_t u;
    asm("cvt.rna.tf32.f32 %0, %1;" : "=r"(u) : "f"(x));
    return __uint_as_float(u);
}
__device__ __forceinline__ uint32_t cvt_tf32_u(float x) {
    uint32_t u;
    asm("cvt.rna.tf32.f32 %0, %1;" : "=r"(u) : "f"(x));
    return u;
}

#define MMA16N8K8(d, a0, a1, a2, a3, b0, b1)                              \
    asm volatile("mma.sync.aligned.m16n8k8.row.col.f32.tf32.tf32.f32 "    \
                 "{%0,%1,%2,%3},{%4,%5,%6,%7},{%8,%9},{%0,%1,%2,%3};"     \
                 : "+f"(d[0]), "+f"(d[1]), "+f"(d[2]), "+f"(d[3])         \
                 : "r"(a0), "r"(a1), "r"(a2), "r"(a3), "r"(b0), "r"(b1))

#define CP16(dst, src) \
    asm volatile("cp.async.cg.shared.global [%0], [%1], 16;" :: "r"(dst), "l"(src))
#define CP_COMMIT() asm volatile("cp.async.commit_group;")
#define CP_WAIT1()  asm volatile("cp.async.wait_group 1;")
#define CP_WAIT0()  asm volatile("cp.async.wait_group 0;")

// ---------------------------------------------------------------------------
// K0: bias transpose  [B][q][k][H] -> g_biasT [B][H][q*k]
// ---------------------------------------------------------------------------
__global__ __launch_bounds__(256) void hp_bias_T(const float* __restrict__ bias)
{
    const size_t qk = (size_t)blockIdx.x * 256 + threadIdx.x;
    const int b = blockIdx.y;
    const float4* p = (const float4*)(bias + ((size_t)b * 1048576 + qk) * 8);
    float4 t0 = p[0];
    float4 t1 = p[1];
    float* o = g_biasT + (size_t)b * 8388608 + qk;
    o[0 * 1048576] = t0.x; o[1 * 1048576] = t0.y;
    o[2 * 1048576] = t0.z; o[3 * 1048576] = t0.w;
    o[4 * 1048576] = t1.x; o[5 * 1048576] = t1.y;
    o[6 * 1048576] = t1.z; o[7 * 1048576] = t1.w;
}

// ---------------------------------------------------------------------------
// K1/K3: tf32 HMMA GEMM, BM=128, BN=128, BK=32, cp.async double-buffered.
// smem: As[2][128][36] + Bs[2][32][136] (raw fp32; cvt at frag load)
// ---------------------------------------------------------------------------
template<int LDN, bool SPLIT>
__global__ __launch_bounds__(256, 2) void hp_gemm_mma(
    const float* __restrict__ Ain, const float* __restrict__ Wm,
    const float* __restrict__ bv, float* __restrict__ outp)
{
    extern __shared__ float sm[];
    float* As = sm;                 // [2][128*36]
    float* Bs = sm + 2 * 128 * 36;  // [2][32*136]

    const float* A = SPLIT ? Ain : g_y;
    const int tid  = threadIdx.x;
    const int warp = tid >> 5, lane = tid & 31;
    const int grp  = lane >> 2, tg = lane & 3;
    const int wm   = warp >> 1, wn = warp & 1;
    const int bm   = blockIdx.y * 128, bn = blockIdx.x * 128;

    const uint32_t sA = (uint32_t)__cvta_generic_to_shared(As);
    const uint32_t sB = (uint32_t)__cvta_generic_to_shared(Bs);

    float acc[2][8][4];
#pragma unroll
    for (int i = 0; i < 2; ++i)
#pragma unroll
        for (int j = 0; j < 8; ++j)
#pragma unroll
            for (int r = 0; r < 4; ++r) acc[i][j][r] = 0.f;

    // tile loader
    auto load_tile = [&](int k0, int buf) {
#pragma unroll
        for (int i = 0; i < 4; ++i) {
            int v = i * 256 + tid;
            int r = v >> 3, c4 = (v & 7) << 2;
            CP16(sA + (buf * 128 * 36 + r * 36 + c4) * 4,
                 &A[(size_t)(bm + r) * 512 + k0 + c4]);
        }
#pragma unroll
        for (int i = 0; i < 4; ++i) {
            int v = i * 256 + tid;
            int r = v >> 5, c4 = (v & 31) << 2;
            CP16(sB + (buf * 32 * 136 + r * 136 + c4) * 4,
                 &Wm[(size_t)(k0 + r) * LDN + bn + c4]);
        }
    };

    load_tile(0, 0);
    CP_COMMIT();

    for (int it = 0; it < 16; ++it) {
        const int cur = it & 1;
        if (it < 15) {
            load_tile((it + 1) * 32, cur ^ 1);
            CP_COMMIT();
            CP_WAIT1();
        } else {
            CP_WAIT0();
        }
        __syncthreads();

        const float* Ac = As + cur * 128 * 36;
        const float* Bc = Bs + cur * 32 * 136;
#pragma unroll
        for (int ks = 0; ks < 4; ++ks) {
            const int kb = ks * 8;
            uint32_t a[2][4];
#pragma unroll
            for (int mf = 0; mf < 2; ++mf) {
                int r = wm * 32 + mf * 16 + grp;
                a[mf][0] = cvt_tf32_u(Ac[r * 36 + kb + tg]);
                a[mf][1] = cvt_tf32_u(Ac[(r + 8) * 36 + kb + tg]);
                a[mf][2] = cvt_tf32_u(Ac[r * 36 + kb + tg + 4]);
                a[mf][3] = cvt_tf32_u(Ac[(r + 8) * 36 + kb + tg + 4]);
            }
#pragma unroll
            for (int nf = 0; nf < 8; ++nf) {
                int c = wn * 64 + nf * 8 + grp;
                uint32_t b0 = cvt_tf32_u(Bc[(kb + tg) * 136 + c]);
                uint32_t b1 = cvt_tf32_u(Bc[(kb + tg + 4) * 136 + c]);
                MMA16N8K8(acc[0][nf], a[0][0], a[0][1], a[0][2], a[0][3], b0, b1);
                MMA16N8K8(acc[1][nf], a[1][0], a[1][1], a[1][2], a[1][3], b0, b1);
            }
        }
        __syncthreads();
    }

#pragma unroll
    for (int mf = 0; mf < 2; ++mf) {
#pragma unroll
        for (int rr = 0; rr < 2; ++rr) {
            const int m = bm + wm * 32 + mf * 16 + grp + rr * 8;
#pragma unroll
            for (int nf = 0; nf < 8; ++nf) {
                const int c = bn + wn * 64 + nf * 8 + tg * 2;
                float v0 = acc[mf][nf][rr * 2]     + bv[c];
                float v1 = acc[mf][nf][rr * 2 + 1] + bv[c + 1];
                if (SPLIT) {
                    int bi = m >> 10, n = m & 1023;
                    int h = c / 192, rem = c - h * 192;
                    int which = rem >> 6, t = rem & 63;
                    if (which == 0) {
                        g_qT[(((size_t)bi * 8 + h) * 64 + t)     * 1024 + n] = v0;
                        g_qT[(((size_t)bi * 8 + h) * 64 + t + 1) * 1024 + n] = v1;
                    } else if (which == 1) {
                        g_kT[(((size_t)bi * 8 + h) * 64 + t)     * 1024 + n] = v0;
                        g_kT[(((size_t)bi * 8 + h) * 64 + t + 1) * 1024 + n] = v1;
                    } else {
                        float2 w2 = make_float2(v0, v1);
                        *(float2*)&g_v[(((size_t)bi * 8 + h) * 1024 + n) * 64 + t] = w2;
                    }
                } else {
                    float2 w2 = make_float2(v0, v1);
                    *(float2*)&outp[(size_t)m * 512 + c] = w2;
                }
            }
        }
    }
}

// ---------------------------------------------------------------------------
// K2: flash attention, tf32 HMMA, cp.async double-buffered K/V/bias tiles.
// Block = (h, 128-q-tile, b), 256 thr, 8 warps; 32-key tiles, 32 iterations.
// smem (dynamic, 96KB): Ks[2][64][40], Vs[2][32][72], Bb[2][128][40], Ps[128][36]
// ---------------------------------------------------------------------------
__global__ __launch_bounds__(256, 2) void hp_attn_mma()
{
    extern __shared__ float sm[];
    float* Ks = sm;                      // 2*64*40  = 5120
    float* Vs = sm + 5120;               // 2*32*72  = 4608
    float* Bb = sm + 9728;               // 2*128*40 = 10240
    float* Ps = sm + 19968;              // 128*36   = 4608

    const int tid  = threadIdx.x;
    const int warp = tid >> 5, lane = tid & 31;
    const int grp  = lane >> 2, tg = lane & 3;
    const int h  = blockIdx.x;
    const int qt = blockIdx.y;
    const int b  = blockIdx.z;
    const int bh = b * HH + h;
    const int q0 = qt * 128;

    const uint32_t sK = (uint32_t)__cvta_generic_to_shared(Ks);
    const uint32_t sV = (uint32_t)__cvta_generic_to_shared(Vs);
    const uint32_t sBb = (uint32_t)__cvta_generic_to_shared(Bb);

    const float* kb = g_kT + (size_t)bh * HD * NN;
    const float* vb = g_v  + (size_t)bh * NN * HD;
    const float* bias_bh = g_biasT + ((size_t)bh << 20);

    auto load_tile = [&](int k0, int buf) {
#pragma unroll
        for (int i = 0; i < 2; ++i) {                 // Ks: 64 x 32
            int v = i * 256 + tid;
            int d = v >> 3, c4 = (v & 7) << 2;
            CP16(sK + (buf * 2560 + d * 40 + c4) * 4,
                 &kb[(size_t)d * NN + k0 + c4]);
        }
#pragma unroll
        for (int i = 0; i < 2; ++i) {                 // Vs: 32 x 64
            int v = i * 256 + tid;
            int r = v >> 4, c4 = (v & 15) << 2;
            CP16(sV + (buf * 2304 + r * 72 + c4) * 4,
                 &vb[(size_t)(k0 + r) * HD + c4]);
        }
#pragma unroll
        for (int i = 0; i < 4; ++i) {                 // Bb: 128 x 32
            int v = i * 256 + tid;
            int r = v >> 3, c4 = (v & 7) << 2;
            CP16(sBb + (buf * 5120 + r * 40 + c4) * 4,
                 &bias_bh[(size_t)(q0 + r) * 1024 + k0 + c4]);
        }
    };

    load_tile(0, 0);
    CP_COMMIT();

    // Q fragments in registers, pre-scaled by 1/sqrt(64)
    const float* qbase = g_qT + (size_t)bh * HD * NN;
    const int qr = q0 + warp * 16 + grp;
    uint32_t qa[8][4];
#pragma unroll
    for (int s = 0; s < 8; ++s) {
        int d0 = s * 8 + tg;
        qa[s][0] = cvt_tf32_u(qbase[(size_t)d0       * NN + qr]     * 0.125f);
        qa[s][1] = cvt_tf32_u(qbase[(size_t)d0       * NN + qr + 8] * 0.125f);
        qa[s][2] = cvt_tf32_u(qbase[(size_t)(d0 + 4) * NN + qr]     * 0.125f);
        qa[s][3] = cvt_tf32_u(qbase[(size_t)(d0 + 4) * NN + qr + 8] * 0.125f);
    }

    float o[8][4];
#pragma unroll
    for (int i = 0; i < 8; ++i)
#pragma unroll
        for (int j = 0; j < 4; ++j) o[i][j] = 0.f;
    float m0 = -1e30f, m1 = -1e30f, l0 = 0.f, l1 = 0.f;

    const int r0 = warp * 16 + grp;

    for (int kt = 0; kt < 32; ++kt) {
        const int cur = kt & 1;
        if (kt < 31) {
            load_tile((kt + 1) * 32, cur ^ 1);
            CP_COMMIT();
            CP_WAIT1();
        } else {
            CP_WAIT0();
        }
        __syncthreads();

        const float* Kc = Ks + cur * 2560;
        const float* Vc = Vs + cur * 2304;
        const float* Bc = Bb + cur * 5120;

        // S = Q K^T
        float s_[4][4];
#pragma unroll
        for (int nf = 0; nf < 4; ++nf)
#pragma unroll
            for (int r = 0; r < 4; ++r) s_[nf][r] = 0.f;
#pragma unroll
        for (int ks = 0; ks < 8; ++ks) {
#pragma unroll
            for (int nf = 0; nf < 4; ++nf) {
                int key = nf * 8 + grp;
                uint32_t b0 = cvt_tf32_u(Kc[(ks * 8 + tg) * 40 + key]);
                uint32_t b1 = cvt_tf32_u(Kc[(ks * 8 + tg + 4) * 40 + key]);
                MMA16N8K8(s_[nf], qa[ks][0], qa[ks][1], qa[ks][2], qa[ks][3], b0, b1);
            }
        }
        // bias add from smem tile
#pragma unroll
        for (int nf = 0; nf < 4; ++nf) {
            int c = nf * 8 + tg * 2;
            float2 t0 = *(const float2*)&Bc[r0 * 40 + c];
            float2 t1 = *(const float2*)&Bc[(r0 + 8) * 40 + c];
            s_[nf][0] += t0.x; s_[nf][1] += t0.y;
            s_[nf][2] += t1.x; s_[nf][3] += t1.y;
        }

        // online softmax
        float mx0 = -1e30f, mx1 = -1e30f;
#pragma unroll
        for (int nf = 0; nf < 4; ++nf) {
            mx0 = fmaxf(mx0, fmaxf(s_[nf][0], s_[nf][1]));
            mx1 = fmaxf(mx1, fmaxf(s_[nf][2], s_[nf][3]));
        }
        mx0 = fmaxf(mx0, __shfl_xor_sync(0xffffffffu, mx0, 1));
        mx0 = fmaxf(mx0, __shfl_xor_sync(0xffffffffu, mx0, 2));
        mx1 = fmaxf(mx1, __shfl_xor_sync(0xffffffffu, mx1, 1));
        mx1 = fmaxf(mx1, __shfl_xor_sync(0xffffffffu, mx1, 2));
        float mn0 = fmaxf(m0, mx0), mn1 = fmaxf(m1, mx1);
        float sc0 = __expf(m0 - mn0), sc1 = __expf(m1 - mn1);
        float sum0 = 0.f, sum1 = 0.f;
#pragma unroll
        for (int nf = 0; nf < 4; ++nf) {
            s_[nf][0] = __expf(s_[nf][0] - mn0);
            s_[nf][1] = __expf(s_[nf][1] - mn0);
            s_[nf][2] = __expf(s_[nf][2] - mn1);
            s_[nf][3] = __expf(s_[nf][3] - mn1);
            sum0 += s_[nf][0] + s_[nf][1];
            sum1 += s_[nf][2] + s_[nf][3];
        }
        sum0 += __shfl_xor_sync(0xffffffffu, sum0, 1);
        sum0 += __shfl_xor_sync(0xffffffffu, sum0, 2);
        sum1 += __shfl_xor_sync(0xffffffffu, sum1, 1);
        sum1 += __shfl_xor_sync(0xffffffffu, sum1, 2);
        l0 = l0 * sc0 + sum0;
        l1 = l1 * sc1 + sum1;
        m0 = mn0; m1 = mn1;

        // rescale O
#pragma unroll
        for (int nf = 0; nf < 8; ++nf) {
            o[nf][0] *= sc0; o[nf][1] *= sc0;
            o[nf][2] *= sc1; o[nf][3] *= sc1;
        }

        // P -> smem (warp-private rows), tf32
#pragma unroll
        for (int nf = 0; nf < 4; ++nf) {
            int c = nf * 8 + tg * 2;
            float2 p0 = make_float2(cvt_tf32(s_[nf][0]), cvt_tf32(s_[nf][1]));
            float2 p1 = make_float2(cvt_tf32(s_[nf][2]), cvt_tf32(s_[nf][3]));
            *(float2*)&Ps[r0 * 36 + c]       = p0;
            *(float2*)&Ps[(r0 + 8) * 36 + c] = p1;
        }
        __syncwarp();

        // O += P V
#pragma unroll
        for (int ks = 0; ks < 4; ++ks) {
            uint32_t a0 = __float_as_uint(Ps[r0 * 36 + ks * 8 + tg]);
            uint32_t a1 = __float_as_uint(Ps[(r0 + 8) * 36 + ks * 8 + tg]);
            uint32_t a2 = __float_as_uint(Ps[r0 * 36 + ks * 8 + tg + 4]);
            uint32_t a3 = __float_as_uint(Ps[(r0 + 8) * 36 + ks * 8 + tg + 4]);
#pragma unroll
            for (int nf = 0; nf < 8; ++nf) {
                int dc = nf * 8 + grp;
                uint32_t b0 = cvt_tf32_u(Vc[(ks * 8 + tg) * 72 + dc]);
                uint32_t b1 = cvt_tf32_u(Vc[(ks * 8 + tg + 4) * 72 + dc]);
                MMA16N8K8(o[nf], a0, a1, a2, a3, b0, b1);
            }
        }
        __syncthreads();
    }

    // epilogue
    const float inv0 = 1.f / l0, inv1 = 1.f / l1;
    const size_t row0 = (size_t)b * NN + q0 + warp * 16 + grp;
    const size_t row1 = row0 + 8;
#pragma unroll
    for (int nf = 0; nf < 8; ++nf) {
        int c = h * 64 + nf * 8 + tg * 2;
        float2 w0 = make_float2(o[nf][0] * inv0, o[nf][1] * inv0);
        float2 w1 = make_float2(o[nf][2] * inv1, o[nf][3] * inv1);
        *(float2*)&g_y[row0 * DD + c] = w0;
        *(float2*)&g_y[row1 * DD + c] = w1;
    }
}

// ---------------------------------------------------------------------------
extern "C" void kernel_launch(void* const* d_in, const int* in_sizes, int n_in,
                              void* d_out, int out_size)
{
    const float* x    = (const float*)d_in[0];
    const float* bias = (const float*)d_in[1];
    const float* Wqkv = (const float*)d_in[2];
    const float* bqkv = (const float*)d_in[3];
    const float* Wo   = (const float*)d_in[4];
    const float* bo   = (const float*)d_in[5];
    float* out = (float*)d_out;

    const int gemm_smem = (2 * 128 * 36 + 2 * 32 * 136) * 4;  // 71680
    const int attn_smem = 24576 * 4;                          // 98304

    cudaFuncSetAttribute(hp_gemm_mma<1536, true>,
                         cudaFuncAttributeMaxDynamicSharedMemorySize, gemm_smem);
    cudaFuncSetAttribute(hp_gemm_mma<512, false>,
                         cudaFuncAttributeMaxDynamicSharedMemorySize, gemm_smem);
    cudaFuncSetAttribute(hp_attn_mma,
                         cudaFuncAttributeMaxDynamicSharedMemorySize, attn_smem);

    hp_bias_T<<<dim3(4096, 8), 256>>>(bias);
    hp_gemm_mma<1536, true ><<<dim3(12, 64), 256, gemm_smem>>>(x, Wqkv, bqkv, nullptr);
    hp_attn_mma<<<dim3(HH, NN / 128, BB), 256, attn_smem>>>();
    hp_gemm_mma<512, false><<<dim3(4, 64), 256, gemm_smem>>>(nullptr, Wo, bo, out);
}

// round 5
// speedup vs baseline: 3.1653x; 1.0604x over previous
#include <cuda_runtime.h>
#include <math.h>
#include <stdint.h>

#define BB 8
#define NN 1024
#define DD 512
#define HH 8
#define HD 64

__device__ float g_qT[BB*HH*HD*NN];    // [B,H,d,n]   16MB (tf32-rounded)
__device__ float g_kT[BB*HH*HD*NN];    // [B,H,d,n]   16MB (tf32-rounded)
__device__ float g_v [BB*HH*NN*HD];    // [B,H,n,d]   16MB (tf32-rounded)
__device__ float g_y [BB*NN*DD];       // [token, D]  16MB (tf32-rounded)
__device__ float g_x [BB*NN*DD];       // pre-rounded x      16MB
__device__ float g_wq[DD*3*DD];        // pre-rounded W_qkv   3MB
__device__ float g_wo[DD*DD];          // pre-rounded W_o     1MB
__device__ float g_biasT[(size_t)BB*HH*NN*NN];  // [B,H,q,k] 268MB

__device__ __forceinline__ float cvt_tf32(float x) {
    uint32_t u;
    asm("cvt.rna.tf32.f32 %0, %1;" : "=r"(u) : "f"(x));
    return __uint_as_float(u);
}

#define MMA16N8K8(d, a0, a1, a2, a3, b0, b1)                              \
    asm volatile("mma.sync.aligned.m16n8k8.row.col.f32.tf32.tf32.f32 "    \
                 "{%0,%1,%2,%3},{%4,%5,%6,%7},{%8,%9},{%0,%1,%2,%3};"     \
                 : "+f"(d[0]), "+f"(d[1]), "+f"(d[2]), "+f"(d[3])         \
                 : "r"(a0), "r"(a1), "r"(a2), "r"(a3), "r"(b0), "r"(b1))

#define CP16(dst, src) \
    asm volatile("cp.async.cg.shared.global [%0], [%1], 16;" :: "r"(dst), "l"(src))
#define CP_COMMIT() asm volatile("cp.async.commit_group;")
#define CP_WAIT1()  asm volatile("cp.async.wait_group 1;")
#define CP_WAIT0()  asm volatile("cp.async.wait_group 0;")

// ---------------------------------------------------------------------------
// K-pre: elementwise tf32 rounding (float4 vectorized)
// ---------------------------------------------------------------------------
__global__ __launch_bounds__(256) void hp_cvt4(const float4* __restrict__ in,
                                               float4* __restrict__ out)
{
    const size_t i = (size_t)blockIdx.x * 256 + threadIdx.x;
    float4 t = in[i];
    t.x = cvt_tf32(t.x); t.y = cvt_tf32(t.y);
    t.z = cvt_tf32(t.z); t.w = cvt_tf32(t.w);
    out[i] = t;
}

// ---------------------------------------------------------------------------
// K0: bias transpose  [B][q][k][H] -> g_biasT [B][H][q*k]
// ---------------------------------------------------------------------------
__global__ __launch_bounds__(256) void hp_bias_T(const float* __restrict__ bias)
{
    const size_t qk = (size_t)blockIdx.x * 256 + threadIdx.x;
    const int b = blockIdx.y;
    const float4* p = (const float4*)(bias + ((size_t)b * 1048576 + qk) * 8);
    float4 t0 = p[0];
    float4 t1 = p[1];
    float* o = g_biasT + (size_t)b * 8388608 + qk;
    o[0 * 1048576] = t0.x; o[1 * 1048576] = t0.y;
    o[2 * 1048576] = t0.z; o[3 * 1048576] = t0.w;
    o[4 * 1048576] = t1.x; o[5 * 1048576] = t1.y;
    o[6 * 1048576] = t1.z; o[7 * 1048576] = t1.w;
}

// ---------------------------------------------------------------------------
// K1/K3: tf32 HMMA GEMM, BM=128, BN=128, BK=32, cp.async double-buffered.
// Inputs pre-rounded to tf32 -> inner loop is pure LDS+MMA (no CVT).
// ---------------------------------------------------------------------------
template<int LDN, bool SPLIT>
__global__ __launch_bounds__(256, 2) void hp_gemm_mma(
    const float* __restrict__ A, const float* __restrict__ Wm,
    const float* __restrict__ bv, float* __restrict__ outp)
{
    extern __shared__ float sm[];
    float* As = sm;                 // [2][128*36]
    float* Bs = sm + 2 * 128 * 36;  // [2][32*136]

    const int tid  = threadIdx.x;
    const int warp = tid >> 5, lane = tid & 31;
    const int grp  = lane >> 2, tg = lane & 3;
    const int wm   = warp >> 1, wn = warp & 1;
    const int bm   = blockIdx.y * 128, bn = blockIdx.x * 128;

    const uint32_t sA = (uint32_t)__cvta_generic_to_shared(As);
    const uint32_t sB = (uint32_t)__cvta_generic_to_shared(Bs);

    float acc[2][8][4];
#pragma unroll
    for (int i = 0; i < 2; ++i)
#pragma unroll
        for (int j = 0; j < 8; ++j)
#pragma unroll
            for (int r = 0; r < 4; ++r) acc[i][j][r] = 0.f;

    auto load_tile = [&](int k0, int buf) {
#pragma unroll
        for (int i = 0; i < 4; ++i) {
            int v = i * 256 + tid;
            int r = v >> 3, c4 = (v & 7) << 2;
            CP16(sA + (buf * 128 * 36 + r * 36 + c4) * 4,
                 &A[(size_t)(bm + r) * 512 + k0 + c4]);
        }
#pragma unroll
        for (int i = 0; i < 4; ++i) {
            int v = i * 256 + tid;
            int r = v >> 5, c4 = (v & 31) << 2;
            CP16(sB + (buf * 32 * 136 + r * 136 + c4) * 4,
                 &Wm[(size_t)(k0 + r) * LDN + bn + c4]);
        }
    };

    load_tile(0, 0);
    CP_COMMIT();

    for (int it = 0; it < 16; ++it) {
        const int cur = it & 1;
        if (it < 15) {
            load_tile((it + 1) * 32, cur ^ 1);
            CP_COMMIT();
            CP_WAIT1();
        } else {
            CP_WAIT0();
        }
        __syncthreads();

        const float* Ac = As + cur * 128 * 36;
        const float* Bc = Bs + cur * 32 * 136;
#pragma unroll
        for (int ks = 0; ks < 4; ++ks) {
            const int kb = ks * 8;
            uint32_t a[2][4];
#pragma unroll
            for (int mf = 0; mf < 2; ++mf) {
                int r = wm * 32 + mf * 16 + grp;
                a[mf][0] = __float_as_uint(Ac[r * 36 + kb + tg]);
                a[mf][1] = __float_as_uint(Ac[(r + 8) * 36 + kb + tg]);
                a[mf][2] = __float_as_uint(Ac[r * 36 + kb + tg + 4]);
                a[mf][3] = __float_as_uint(Ac[(r + 8) * 36 + kb + tg + 4]);
            }
#pragma unroll
            for (int nf = 0; nf < 8; ++nf) {
                int c = wn * 64 + nf * 8 + grp;
                uint32_t b0 = __float_as_uint(Bc[(kb + tg) * 136 + c]);
                uint32_t b1 = __float_as_uint(Bc[(kb + tg + 4) * 136 + c]);
                MMA16N8K8(acc[0][nf], a[0][0], a[0][1], a[0][2], a[0][3], b0, b1);
                MMA16N8K8(acc[1][nf], a[1][0], a[1][1], a[1][2], a[1][3], b0, b1);
            }
        }
        __syncthreads();
    }

#pragma unroll
    for (int mf = 0; mf < 2; ++mf) {
#pragma unroll
        for (int rr = 0; rr < 2; ++rr) {
            const int m = bm + wm * 32 + mf * 16 + grp + rr * 8;
#pragma unroll
            for (int nf = 0; nf < 8; ++nf) {
                const int c = bn + wn * 64 + nf * 8 + tg * 2;
                float v0 = acc[mf][nf][rr * 2]     + bv[c];
                float v1 = acc[mf][nf][rr * 2 + 1] + bv[c + 1];
                if (SPLIT) {
                    // round q/k/v to tf32 here: attention consumes raw bits
                    v0 = cvt_tf32(v0);
                    v1 = cvt_tf32(v1);
                    int bi = m >> 10, n = m & 1023;
                    int h = c / 192, rem = c - h * 192;
                    int which = rem >> 6, t = rem & 63;
                    if (which == 0) {
                        g_qT[(((size_t)bi * 8 + h) * 64 + t)     * 1024 + n] = v0;
                        g_qT[(((size_t)bi * 8 + h) * 64 + t + 1) * 1024 + n] = v1;
                    } else if (which == 1) {
                        g_kT[(((size_t)bi * 8 + h) * 64 + t)     * 1024 + n] = v0;
                        g_kT[(((size_t)bi * 8 + h) * 64 + t + 1) * 1024 + n] = v1;
                    } else {
                        float2 w2 = make_float2(v0, v1);
                        *(float2*)&g_v[(((size_t)bi * 8 + h) * 1024 + n) * 64 + t] = w2;
                    }
                } else {
                    float2 w2 = make_float2(v0, v1);
                    *(float2*)&outp[(size_t)m * 512 + c] = w2;
                }
            }
        }
    }
}

// ---------------------------------------------------------------------------
// K2: flash attention, tf32 HMMA, cp.async double-buffered K/V/bias tiles.
// All MMA operands pre-rounded -> no CVT in the loop (bias adds in fp32).
// ---------------------------------------------------------------------------
__global__ __launch_bounds__(256, 2) void hp_attn_mma()
{
    extern __shared__ float sm[];
    float* Ks = sm;                      // 2*64*40  = 5120
    float* Vs = sm + 5120;               // 2*32*72  = 4608
    float* Bb = sm + 9728;               // 2*128*40 = 10240
    float* Ps = sm + 19968;              // 128*36   = 4608

    const int tid  = threadIdx.x;
    const int warp = tid >> 5, lane = tid & 31;
    const int grp  = lane >> 2, tg = lane & 3;
    const int h  = blockIdx.x;
    const int qt = blockIdx.y;
    const int b  = blockIdx.z;
    const int bh = b * HH + h;
    const int q0 = qt * 128;

    const uint32_t sK = (uint32_t)__cvta_generic_to_shared(Ks);
    const uint32_t sV = (uint32_t)__cvta_generic_to_shared(Vs);
    const uint32_t sBb = (uint32_t)__cvta_generic_to_shared(Bb);

    const float* kb = g_kT + (size_t)bh * HD * NN;
    const float* vb = g_v  + (size_t)bh * NN * HD;
    const float* bias_bh = g_biasT + ((size_t)bh << 20);

    auto load_tile = [&](int k0, int buf) {
#pragma unroll
        for (int i = 0; i < 2; ++i) {                 // Ks: 64 x 32
            int v = i * 256 + tid;
            int d = v >> 3, c4 = (v & 7) << 2;
            CP16(sK + (buf * 2560 + d * 40 + c4) * 4,
                 &kb[(size_t)d * NN + k0 + c4]);
        }
#pragma unroll
        for (int i = 0; i < 2; ++i) {                 // Vs: 32 x 64
            int v = i * 256 + tid;
            int r = v >> 4, c4 = (v & 15) << 2;
            CP16(sV + (buf * 2304 + r * 72 + c4) * 4,
                 &vb[(size_t)(k0 + r) * HD + c4]);
        }
#pragma unroll
        for (int i = 0; i < 4; ++i) {                 // Bb: 128 x 32
            int v = i * 256 + tid;
            int r = v >> 3, c4 = (v & 7) << 2;
            CP16(sBb + (buf * 5120 + r * 40 + c4) * 4,
                 &bias_bh[(size_t)(q0 + r) * 1024 + k0 + c4]);
        }
    };

    load_tile(0, 0);
    CP_COMMIT();

    // Q fragments (pre-rounded tf32; *0.125f is exact exponent shift)
    const float* qbase = g_qT + (size_t)bh * HD * NN;
    const int qr = q0 + warp * 16 + grp;
    uint32_t qa[8][4];
#pragma unroll
    for (int s = 0; s < 8; ++s) {
        int d0 = s * 8 + tg;
        qa[s][0] = __float_as_uint(qbase[(size_t)d0       * NN + qr]     * 0.125f);
        qa[s][1] = __float_as_uint(qbase[(size_t)d0       * NN + qr + 8] * 0.125f);
        qa[s][2] = __float_as_uint(qbase[(size_t)(d0 + 4) * NN + qr]     * 0.125f);
        qa[s][3] = __float_as_uint(qbase[(size_t)(d0 + 4) * NN + qr + 8] * 0.125f);
    }

    float o[8][4];
#pragma unroll
    for (int i = 0; i < 8; ++i)
#pragma unroll
        for (int j = 0; j < 4; ++j) o[i][j] = 0.f;
    float m0 = -1e30f, m1 = -1e30f, l0 = 0.f, l1 = 0.f;

    const int r0 = warp * 16 + grp;

    for (int kt = 0; kt < 32; ++kt) {
        const int cur = kt & 1;
        if (kt < 31) {
            load_tile((kt + 1) * 32, cur ^ 1);
            CP_COMMIT();
            CP_WAIT1();
        } else {
            CP_WAIT0();
        }
        __syncthreads();

        const float* Kc = Ks + cur * 2560;
        const float* Vc = Vs + cur * 2304;
        const float* Bc = Bb + cur * 5120;

        // S = Q K^T
        float s_[4][4];
#pragma unroll
        for (int nf = 0; nf < 4; ++nf)
#pragma unroll
            for (int r = 0; r < 4; ++r) s_[nf][r] = 0.f;
#pragma unroll
        for (int ks = 0; ks < 8; ++ks) {
#pragma unroll
            for (int nf = 0; nf < 4; ++nf) {
                int key = nf * 8 + grp;
                uint32_t b0 = __float_as_uint(Kc[(ks * 8 + tg) * 40 + key]);
                uint32_t b1 = __float_as_uint(Kc[(ks * 8 + tg + 4) * 40 + key]);
                MMA16N8K8(s_[nf], qa[ks][0], qa[ks][1], qa[ks][2], qa[ks][3], b0, b1);
            }
        }
        // bias add from smem tile (fp32, not an MMA operand: no rounding)
#pragma unroll
        for (int nf = 0; nf < 4; ++nf) {
            int c = nf * 8 + tg * 2;
            float2 t0 = *(const float2*)&Bc[r0 * 40 + c];
            float2 t1 = *(const float2*)&Bc[(r0 + 8) * 40 + c];
            s_[nf][0] += t0.x; s_[nf][1] += t0.y;
            s_[nf][2] += t1.x; s_[nf][3] += t1.y;
        }

        // online softmax
        float mx0 = -1e30f, mx1 = -1e30f;
#pragma unroll
        for (int nf = 0; nf < 4; ++nf) {
            mx0 = fmaxf(mx0, fmaxf(s_[nf][0], s_[nf][1]));
            mx1 = fmaxf(mx1, fmaxf(s_[nf][2], s_[nf][3]));
        }
        mx0 = fmaxf(mx0, __shfl_xor_sync(0xffffffffu, mx0, 1));
        mx0 = fmaxf(mx0, __shfl_xor_sync(0xffffffffu, mx0, 2));
        mx1 = fmaxf(mx1, __shfl_xor_sync(0xffffffffu, mx1, 1));
        mx1 = fmaxf(mx1, __shfl_xor_sync(0xffffffffu, mx1, 2));
        float mn0 = fmaxf(m0, mx0), mn1 = fmaxf(m1, mx1);
        float sc0 = __expf(m0 - mn0), sc1 = __expf(m1 - mn1);
        float sum0 = 0.f, sum1 = 0.f;
#pragma unroll
        for (int nf = 0; nf < 4; ++nf) {
            s_[nf][0] = __expf(s_[nf][0] - mn0);
            s_[nf][1] = __expf(s_[nf][1] - mn0);
            s_[nf][2] = __expf(s_[nf][2] - mn1);
            s_[nf][3] = __expf(s_[nf][3] - mn1);
            sum0 += s_[nf][0] + s_[nf][1];
            sum1 += s_[nf][2] + s_[nf][3];
        }
        sum0 += __shfl_xor_sync(0xffffffffu, sum0, 1);
        sum0 += __shfl_xor_sync(0xffffffffu, sum0, 2);
        sum1 += __shfl_xor_sync(0xffffffffu, sum1, 1);
        sum1 += __shfl_xor_sync(0xffffffffu, sum1, 2);
        l0 = l0 * sc0 + sum0;
        l1 = l1 * sc1 + sum1;
        m0 = mn0; m1 = mn1;

        // rescale O
#pragma unroll
        for (int nf = 0; nf < 8; ++nf) {
            o[nf][0] *= sc0; o[nf][1] *= sc0;
            o[nf][2] *= sc1; o[nf][3] *= sc1;
        }

        // P -> smem (warp-private rows), rounded to tf32 once here
#pragma unroll
        for (int nf = 0; nf < 4; ++nf) {
            int c = nf * 8 + tg * 2;
            float2 p0 = make_float2(cvt_tf32(s_[nf][0]), cvt_tf32(s_[nf][1]));
            float2 p1 = make_float2(cvt_tf32(s_[nf][2]), cvt_tf32(s_[nf][3]));
            *(float2*)&Ps[r0 * 36 + c]       = p0;
            *(float2*)&Ps[(r0 + 8) * 36 + c] = p1;
        }
        __syncwarp();

        // O += P V
#pragma unroll
        for (int ks = 0; ks < 4; ++ks) {
            uint32_t a0 = __float_as_uint(Ps[r0 * 36 + ks * 8 + tg]);
            uint32_t a1 = __float_as_uint(Ps[(r0 + 8) * 36 + ks * 8 + tg]);
            uint32_t a2 = __float_as_uint(Ps[r0 * 36 + ks * 8 + tg + 4]);
            uint32_t a3 = __float_as_uint(Ps[(r0 + 8) * 36 + ks * 8 + tg + 4]);
#pragma unroll
            for (int nf = 0; nf < 8; ++nf) {
                int dc = nf * 8 + grp;
                uint32_t b0 = __float_as_uint(Vc[(ks * 8 + tg) * 72 + dc]);
                uint32_t b1 = __float_as_uint(Vc[(ks * 8 + tg + 4) * 72 + dc]);
                MMA16N8K8(o[nf], a0, a1, a2, a3, b0, b1);
            }
        }
        __syncthreads();
    }

    // epilogue: round to tf32 for the output GEMM's A operand
    const float inv0 = 1.f / l0, inv1 = 1.f / l1;
    const size_t row0 = (size_t)b * NN + q0 + warp * 16 + grp;
    const size_t row1 = row0 + 8;
#pragma unroll
    for (int nf = 0; nf < 8; ++nf) {
        int c = h * 64 + nf * 8 + tg * 2;
        float2 w0 = make_float2(cvt_tf32(o[nf][0] * inv0), cvt_tf32(o[nf][1] * inv0));
        float2 w1 = make_float2(cvt_tf32(o[nf][2] * inv1), cvt_tf32(o[nf][3] * inv1));
        *(float2*)&g_y[row0 * DD + c] = w0;
        *(float2*)&g_y[row1 * DD + c] = w1;
    }
}

// ---------------------------------------------------------------------------
extern "C" void kernel_launch(void* const* d_in, const int* in_sizes, int n_in,
                              void* d_out, int out_size)
{
    const float* x    = (const float*)d_in[0];
    const float* bias = (const float*)d_in[1];
    const float* Wqkv = (const float*)d_in[2];
    const float* bqkv = (const float*)d_in[3];
    const float* Wo   = (const float*)d_in[4];
    const float* bo   = (const float*)d_in[5];
    float* out = (float*)d_out;

    const int gemm_smem = (2 * 128 * 36 + 2 * 32 * 136) * 4;  // 71680
    const int attn_smem = 24576 * 4;                          // 98304

    cudaFuncSetAttribute(hp_gemm_mma<1536, true>,
                         cudaFuncAttributeMaxDynamicSharedMemorySize, gemm_smem);
    cudaFuncSetAttribute(hp_gemm_mma<512, false>,
                         cudaFuncAttributeMaxDynamicSharedMemorySize, gemm_smem);
    cudaFuncSetAttribute(hp_attn_mma,
                         cudaFuncAttributeMaxDynamicSharedMemorySize, attn_smem);

    float* gx;  cudaGetSymbolAddress((void**)&gx,  g_x);
    float* gwq; cudaGetSymbolAddress((void**)&gwq, g_wq);
    float* gwo; cudaGetSymbolAddress((void**)&gwo, g_wo);
    float* gy;  cudaGetSymbolAddress((void**)&gy,  g_y);   // FIX: out-GEMM A operand

    // pre-round external inputs to tf32 (RNA)
    hp_cvt4<<<BB*NN*DD/4/256, 256>>>((const float4*)x,    (float4*)gx);
    hp_cvt4<<<DD*3*DD/4/256, 256>>>((const float4*)Wqkv, (float4*)gwq);
    hp_cvt4<<<DD*DD/4/256,   256>>>((const float4*)Wo,   (float4*)gwo);

    hp_bias_T<<<dim3(4096, 8), 256>>>(bias);
    hp_gemm_mma<1536, true ><<<dim3(12, 64), 256, gemm_smem>>>(gx, gwq, bqkv, nullptr);
    hp_attn_mma<<<dim3(HH, NN / 128, BB), 256, attn_smem>>>();
    hp_gemm_mma<512, false><<<dim3(4, 64), 256, gemm_smem>>>(gy, gwo, bo, out);
}

// round 7
// speedup vs baseline: 3.1661x; 1.0003x over previous
#include <cuda_runtime.h>
#include <math.h>
#include <stdint.h>

#define BB 8
#define NN 1024
#define DD 512
#define HH 8
#define HD 64

__device__ float g_qT[BB*HH*HD*NN];    // [B,H,d,n]   16MB (tf32-rounded)
__device__ float g_kT[BB*HH*HD*NN];    // [B,H,d,n]   16MB (tf32-rounded)
__device__ float g_v [BB*HH*NN*HD];    // [B,H,n,d]   16MB (tf32-rounded)
__device__ float g_y [BB*NN*DD];       // [token, D]  16MB (tf32-rounded)
__device__ float g_x [BB*NN*DD];       // pre-rounded x      16MB
__device__ float g_wq[DD*3*DD];        // pre-rounded W_qkv   3MB
__device__ float g_wo[DD*DD];          // pre-rounded W_o     1MB
__device__ float g_biasT[(size_t)BB*HH*NN*NN];  // [B,H,q,k] 268MB

__device__ __forceinline__ float cvt_tf32(float x) {
    uint32_t u;
    asm("cvt.rna.tf32.f32 %0, %1;" : "=r"(u) : "f"(x));
    return __uint_as_float(u);
}

#define MMA16N8K8(d, a0, a1, a2, a3, b0, b1)                              \
    asm volatile("mma.sync.aligned.m16n8k8.row.col.f32.tf32.tf32.f32 "    \
                 "{%0,%1,%2,%3},{%4,%5,%6,%7},{%8,%9},{%0,%1,%2,%3};"     \
                 : "+f"(d[0]), "+f"(d[1]), "+f"(d[2]), "+f"(d[3])         \
                 : "r"(a0), "r"(a1), "r"(a2), "r"(a3), "r"(b0), "r"(b1))

#define CP16(dst, src) \
    asm volatile("cp.async.cg.shared.global [%0], [%1], 16;" :: "r"(dst), "l"(src))
#define CP_COMMIT() asm volatile("cp.async.commit_group;")
#define CP_WAIT1()  asm volatile("cp.async.wait_group 1;")
#define CP_WAIT0()  asm volatile("cp.async.wait_group 0;")

// ---------------------------------------------------------------------------
// K-pre: elementwise tf32 rounding (float4 vectorized)
// ---------------------------------------------------------------------------
__global__ __launch_bounds__(256) void hp_cvt4(const float4* __restrict__ in,
                                               float4* __restrict__ out)
{
    const size_t i = (size_t)blockIdx.x * 256 + threadIdx.x;
    float4 t = in[i];
    t.x = cvt_tf32(t.x); t.y = cvt_tf32(t.y);
    t.z = cvt_tf32(t.z); t.w = cvt_tf32(t.w);
    out[i] = t;
}

// ---------------------------------------------------------------------------
// K0: bias transpose  [B][q][k][H] -> g_biasT [B][H][q*k]
// ---------------------------------------------------------------------------
__global__ __launch_bounds__(256) void hp_bias_T(const float* __restrict__ bias)
{
    const size_t qk = (size_t)blockIdx.x * 256 + threadIdx.x;
    const int b = blockIdx.y;
    const float4* p = (const float4*)(bias + ((size_t)b * 1048576 + qk) * 8);
    float4 t0 = p[0];
    float4 t1 = p[1];
    float* o = g_biasT + (size_t)b * 8388608 + qk;
    o[0 * 1048576] = t0.x; o[1 * 1048576] = t0.y;
    o[2 * 1048576] = t0.z; o[3 * 1048576] = t0.w;
    o[4 * 1048576] = t1.x; o[5 * 1048576] = t1.y;
    o[6 * 1048576] = t1.z; o[7 * 1048576] = t1.w;
}

// ---------------------------------------------------------------------------
// K1/K3: tf32 HMMA GEMM, BM=128, BN=128, BK=32, cp.async double-buffered.
// Inputs pre-rounded to tf32 -> inner loop is pure LDS+MMA (no CVT).
// ---------------------------------------------------------------------------
template<int LDN, bool SPLIT>
__global__ __launch_bounds__(256, 2) void hp_gemm_mma(
    const float* __restrict__ A, const float* __restrict__ Wm,
    const float* __restrict__ bv, float* __restrict__ outp)
{
    extern __shared__ float sm[];
    float* As = sm;                 // [2][128*36]
    float* Bs = sm + 2 * 128 * 36;  // [2][32*136]

    const int tid  = threadIdx.x;
    const int warp = tid >> 5, lane = tid & 31;
    const int grp  = lane >> 2, tg = lane & 3;
    const int wm   = warp >> 1, wn = warp & 1;
    const int bm   = blockIdx.y * 128, bn = blockIdx.x * 128;

    const uint32_t sA = (uint32_t)__cvta_generic_to_shared(As);
    const uint32_t sB = (uint32_t)__cvta_generic_to_shared(Bs);

    float acc[2][8][4];
#pragma unroll
    for (int i = 0; i < 2; ++i)
#pragma unroll
        for (int j = 0; j < 8; ++j)
#pragma unroll
            for (int r = 0; r < 4; ++r) acc[i][j][r] = 0.f;

    auto load_tile = [&](int k0, int buf) {
#pragma unroll
        for (int i = 0; i < 4; ++i) {
            int v = i * 256 + tid;
            int r = v >> 3, c4 = (v & 7) << 2;
            CP16(sA + (buf * 128 * 36 + r * 36 + c4) * 4,
                 &A[(size_t)(bm + r) * 512 + k0 + c4]);
        }
#pragma unroll
        for (int i = 0; i < 4; ++i) {
            int v = i * 256 + tid;
            int r = v >> 5, c4 = (v & 31) << 2;
            CP16(sB + (buf * 32 * 136 + r * 136 + c4) * 4,
                 &Wm[(size_t)(k0 + r) * LDN + bn + c4]);
        }
    };

    load_tile(0, 0);
    CP_COMMIT();

    for (int it = 0; it < 16; ++it) {
        const int cur = it & 1;
        if (it < 15) {
            load_tile((it + 1) * 32, cur ^ 1);
            CP_COMMIT();
            CP_WAIT1();
        } else {
            CP_WAIT0();
        }
        __syncthreads();

        const float* Ac = As + cur * 128 * 36;
        const float* Bc = Bs + cur * 32 * 136;
#pragma unroll
        for (int ks = 0; ks < 4; ++ks) {
            const int kb = ks * 8;
            uint32_t a[2][4];
#pragma unroll
            for (int mf = 0; mf < 2; ++mf) {
                int r = wm * 32 + mf * 16 + grp;
                a[mf][0] = __float_as_uint(Ac[r * 36 + kb + tg]);
                a[mf][1] = __float_as_uint(Ac[(r + 8) * 36 + kb + tg]);
                a[mf][2] = __float_as_uint(Ac[r * 36 + kb + tg + 4]);
                a[mf][3] = __float_as_uint(Ac[(r + 8) * 36 + kb + tg + 4]);
            }
#pragma unroll
            for (int nf = 0; nf < 8; ++nf) {
                int c = wn * 64 + nf * 8 + grp;
                uint32_t b0 = __float_as_uint(Bc[(kb + tg) * 136 + c]);
                uint32_t b1 = __float_as_uint(Bc[(kb + tg + 4) * 136 + c]);
                MMA16N8K8(acc[0][nf], a[0][0], a[0][1], a[0][2], a[0][3], b0, b1);
                MMA16N8K8(acc[1][nf], a[1][0], a[1][1], a[1][2], a[1][3], b0, b1);
            }
        }
        __syncthreads();
    }

#pragma unroll
    for (int mf = 0; mf < 2; ++mf) {
#pragma unroll
        for (int rr = 0; rr < 2; ++rr) {
            const int m = bm + wm * 32 + mf * 16 + grp + rr * 8;
#pragma unroll
            for (int nf = 0; nf < 8; ++nf) {
                const int c = bn + wn * 64 + nf * 8 + tg * 2;
                float v0 = acc[mf][nf][rr * 2]     + bv[c];
                float v1 = acc[mf][nf][rr * 2 + 1] + bv[c + 1];
                if (SPLIT) {
                    v0 = cvt_tf32(v0);
                    v1 = cvt_tf32(v1);
                    int bi = m >> 10, n = m & 1023;
                    int h = c / 192, rem = c - h * 192;
                    int which = rem >> 6, t = rem & 63;
                    if (which == 0) {
                        g_qT[(((size_t)bi * 8 + h) * 64 + t)     * 1024 + n] = v0;
                        g_qT[(((size_t)bi * 8 + h) * 64 + t + 1) * 1024 + n] = v1;
                    } else if (which == 1) {
                        g_kT[(((size_t)bi * 8 + h) * 64 + t)     * 1024 + n] = v0;
                        g_kT[(((size_t)bi * 8 + h) * 64 + t + 1) * 1024 + n] = v1;
                    } else {
                        float2 w2 = make_float2(v0, v1);
                        *(float2*)&g_v[(((size_t)bi * 8 + h) * 1024 + n) * 64 + t] = w2;
                    }
                } else {
                    float2 w2 = make_float2(v0, v1);
                    *(float2*)&outp[(size_t)m * 512 + c] = w2;
                }
            }
        }
    }
}

// ---------------------------------------------------------------------------
// K2: flash attention, tf32 HMMA, cp.async double-buffered K/V/bias tiles.
// ---------------------------------------------------------------------------
__global__ __launch_bounds__(256, 2) void hp_attn_mma()
{
    extern __shared__ float sm[];
    float* Ks = sm;                      // 2*64*40  = 5120
    float* Vs = sm + 5120;               // 2*32*72  = 4608
    float* Bb = sm + 9728;               // 2*128*40 = 10240
    float* Ps = sm + 19968;              // 128*36   = 4608

    const int tid  = threadIdx.x;
    const int warp = tid >> 5, lane = tid & 31;
    const int grp  = lane >> 2, tg = lane & 3;
    const int h  = blockIdx.x;
    const int qt = blockIdx.y;
    const int b  = blockIdx.z;
    const int bh = b * HH + h;
    const int q0 = qt * 128;

    const uint32_t sK = (uint32_t)__cvta_generic_to_shared(Ks);
    const uint32_t sV = (uint32_t)__cvta_generic_to_shared(Vs);
    const uint32_t sBb = (uint32_t)__cvta_generic_to_shared(Bb);

    const float* kb = g_kT + (size_t)bh * HD * NN;
    const float* vb = g_v  + (size_t)bh * NN * HD;
    const float* bias_bh = g_biasT + ((size_t)bh << 20);

    auto load_tile = [&](int k0, int buf) {
#pragma unroll
        for (int i = 0; i < 2; ++i) {                 // Ks: 64 x 32
            int v = i * 256 + tid;
            int d = v >> 3, c4 = (v & 7) << 2;
            CP16(sK + (buf * 2560 + d * 40 + c4) * 4,
                 &kb[(size_t)d * NN + k0 + c4]);
        }
#pragma unroll
        for (int i = 0; i < 2; ++i) {                 // Vs: 32 x 64
            int v = i * 256 + tid;
            int r = v >> 4, c4 = (v & 15) << 2;
            CP16(sV + (buf * 2304 + r * 72 + c4) * 4,
                 &vb[(size_t)(k0 + r) * HD + c4]);
        }
#pragma unroll
        for (int i = 0; i < 4; ++i) {                 // Bb: 128 x 32
            int v = i * 256 + tid;
            int r = v >> 3, c4 = (v & 7) << 2;
            CP16(sBb + (buf * 5120 + r * 40 + c4) * 4,
                 &bias_bh[(size_t)(q0 + r) * 1024 + k0 + c4]);
        }
    };

    load_tile(0, 0);
    CP_COMMIT();

    const float* qbase = g_qT + (size_t)bh * HD * NN;
    const int qr = q0 + warp * 16 + grp;
    uint32_t qa[8][4];
#pragma unroll
    for (int s = 0; s < 8; ++s) {
        int d0 = s * 8 + tg;
        qa[s][0] = __float_as_uint(qbase[(size_t)d0       * NN + qr]     * 0.125f);
        qa[s][1] = __float_as_uint(qbase[(size_t)d0       * NN + qr + 8] * 0.125f);
        qa[s][2] = __float_as_uint(qbase[(size_t)(d0 + 4) * NN + qr]     * 0.125f);
        qa[s][3] = __float_as_uint(qbase[(size_t)(d0 + 4) * NN + qr + 8] * 0.125f);
    }

    float o[8][4];
#pragma unroll
    for (int i = 0; i < 8; ++i)
#pragma unroll
        for (int j = 0; j < 4; ++j) o[i][j] = 0.f;
    float m0 = -1e30f, m1 = -1e30f, l0 = 0.f, l1 = 0.f;

    const int r0 = warp * 16 + grp;

    for (int kt = 0; kt < 32; ++kt) {
        const int cur = kt & 1;
        if (kt < 31) {
            load_tile((kt + 1) * 32, cur ^ 1);
            CP_COMMIT();
            CP_WAIT1();
        } else {
            CP_WAIT0();
        }
        __syncthreads();

        const float* Kc = Ks + cur * 2560;
        const float* Vc = Vs + cur * 2304;
        const float* Bc = Bb + cur * 5120;

        float s_[4][4];
#pragma unroll
        for (int nf = 0; nf < 4; ++nf)
#pragma unroll
            for (int r = 0; r < 4; ++r) s_[nf][r] = 0.f;
#pragma unroll
        for (int ks = 0; ks < 8; ++ks) {
#pragma unroll
            for (int nf = 0; nf < 4; ++nf) {
                int key = nf * 8 + grp;
                uint32_t b0 = __float_as_uint(Kc[(ks * 8 + tg) * 40 + key]);
                uint32_t b1 = __float_as_uint(Kc[(ks * 8 + tg + 4) * 40 + key]);
                MMA16N8K8(s_[nf], qa[ks][0], qa[ks][1], qa[ks][2], qa[ks][3], b0, b1);
            }
        }
#pragma unroll
        for (int nf = 0; nf < 4; ++nf) {
            int c = nf * 8 + tg * 2;
            float2 t0 = *(const float2*)&Bc[r0 * 40 + c];
            float2 t1 = *(const float2*)&Bc[(r0 + 8) * 40 + c];
            s_[nf][0] += t0.x; s_[nf][1] += t0.y;
            s_[nf][2] += t1.x; s_[nf][3] += t1.y;
        }

        float mx0 = -1e30f, mx1 = -1e30f;
#pragma unroll
        for (int nf = 0; nf < 4; ++nf) {
            mx0 = fmaxf(mx0, fmaxf(s_[nf][0], s_[nf][1]));
            mx1 = fmaxf(mx1, fmaxf(s_[nf][2], s_[nf][3]));
        }
        mx0 = fmaxf(mx0, __shfl_xor_sync(0xffffffffu, mx0, 1));
        mx0 = fmaxf(mx0, __shfl_xor_sync(0xffffffffu, mx0, 2));
        mx1 = fmaxf(mx1, __shfl_xor_sync(0xffffffffu, mx1, 1));
        mx1 = fmaxf(mx1, __shfl_xor_sync(0xffffffffu, mx1, 2));
        float mn0 = fmaxf(m0, mx0), mn1 = fmaxf(m1, mx1);
        float sc0 = __expf(m0 - mn0), sc1 = __expf(m1 - mn1);
        float sum0 = 0.f, sum1 = 0.f;
#pragma unroll
        for (int nf = 0; nf < 4; ++nf) {
            s_[nf][0] = __expf(s_[nf][0] - mn0);
            s_[nf][1] = __expf(s_[nf][1] - mn0);
            s_[nf][2] = __expf(s_[nf][2] - mn1);
            s_[nf][3] = __expf(s_[nf][3] - mn1);
            sum0 += s_[nf][0] + s_[nf][1];
            sum1 += s_[nf][2] + s_[nf][3];
        }
        sum0 += __shfl_xor_sync(0xffffffffu, sum0, 1);
        sum0 += __shfl_xor_sync(0xffffffffu, sum0, 2);
        sum1 += __shfl_xor_sync(0xffffffffu, sum1, 1);
        sum1 += __shfl_xor_sync(0xffffffffu, sum1, 2);
        l0 = l0 * sc0 + sum0;
        l1 = l1 * sc1 + sum1;
        m0 = mn0; m1 = mn1;

#pragma unroll
        for (int nf = 0; nf < 8; ++nf) {
            o[nf][0] *= sc0; o[nf][1] *= sc0;
            o[nf][2] *= sc1; o[nf][3] *= sc1;
        }

#pragma unroll
        for (int nf = 0; nf < 4; ++nf) {
            int c = nf * 8 + tg * 2;
            float2 p0 = make_float2(cvt_tf32(s_[nf][0]), cvt_tf32(s_[nf][1]));
            float2 p1 = make_float2(cvt_tf32(s_[nf][2]), cvt_tf32(s_[nf][3]));
            *(float2*)&Ps[r0 * 36 + c]       = p0;
            *(float2*)&Ps[(r0 + 8) * 36 + c] = p1;
        }
        __syncwarp();

#pragma unroll
        for (int ks = 0; ks < 4; ++ks) {
            uint32_t a0 = __float_as_uint(Ps[r0 * 36 + ks * 8 + tg]);
            uint32_t a1 = __float_as_uint(Ps[(r0 + 8) * 36 + ks * 8 + tg]);
            uint32_t a2 = __float_as_uint(Ps[r0 * 36 + ks * 8 + tg + 4]);
            uint32_t a3 = __float_as_uint(Ps[(r0 + 8) * 36 + ks * 8 + tg + 4]);
#pragma unroll
            for (int nf = 0; nf < 8; ++nf) {
                int dc = nf * 8 + grp;
                uint32_t b0 = __float_as_uint(Vc[(ks * 8 + tg) * 72 + dc]);
                uint32_t b1 = __float_as_uint(Vc[(ks * 8 + tg + 4) * 72 + dc]);
                MMA16N8K8(o[nf], a0, a1, a2, a3, b0, b1);
            }
        }
        __syncthreads();
    }

    const float inv0 = 1.f / l0, inv1 = 1.f / l1;
    const size_t row0 = (size_t)b * NN + q0 + warp * 16 + grp;
    const size_t row1 = row0 + 8;
#pragma unroll
    for (int nf = 0; nf < 8; ++nf) {
        int c = h * 64 + nf * 8 + tg * 2;
        float2 w0 = make_float2(cvt_tf32(o[nf][0] * inv0), cvt_tf32(o[nf][1] * inv0));
        float2 w1 = make_float2(cvt_tf32(o[nf][2] * inv1), cvt_tf32(o[nf][3] * inv1));
        *(float2*)&g_y[row0 * DD + c] = w0;
        *(float2*)&g_y[row1 * DD + c] = w1;
    }
}

// ---------------------------------------------------------------------------
extern "C" void kernel_launch(void* const* d_in, const int* in_sizes, int n_in,
                              void* d_out, int out_size)
{
    const float* x    = (const float*)d_in[0];
    const float* bias = (const float*)d_in[1];
    const float* Wqkv = (const float*)d_in[2];
    const float* bqkv = (const float*)d_in[3];
    const float* Wo   = (const float*)d_in[4];
    const float* bo   = (const float*)d_in[5];
    float* out = (float*)d_out;

    const int gemm_smem = (2 * 128 * 36 + 2 * 32 * 136) * 4;  // 71680
    const int attn_smem = 24576 * 4;                          // 98304

    cudaFuncSetAttribute(hp_gemm_mma<1536, true>,
                         cudaFuncAttributeMaxDynamicSharedMemorySize, gemm_smem);
    cudaFuncSetAttribute(hp_gemm_mma<512, false>,
                         cudaFuncAttributeMaxDynamicSharedMemorySize, gemm_smem);
    cudaFuncSetAttribute(hp_attn_mma,
                         cudaFuncAttributeMaxDynamicSharedMemorySize, attn_smem);

    float* gx;  cudaGetSymbolAddress((void**)&gx,  g_x);
    float* gwq; cudaGetSymbolAddress((void**)&gwq, g_wq);
    float* gwo; cudaGetSymbolAddress((void**)&gwo, g_wo);
    float* gy;  cudaGetSymbolAddress((void**)&gy,  g_y);

    // Fork a side stream: bias transpose (DRAM-bound) runs concurrently with
    // the cvt preludes + QKV GEMM (tensor-bound). Joined before attention.
    cudaStream_t s1;
    cudaStreamCreateWithFlags(&s1, cudaStreamNonBlocking);
    cudaEvent_t eFork, eJoin;
    cudaEventCreateWithFlags(&eFork, cudaEventDisableTiming);
    cudaEventCreateWithFlags(&eJoin, cudaEventDisableTiming);

    cudaEventRecord(eFork, 0);
    cudaStreamWaitEvent(s1, eFork, 0);
    hp_bias_T<<<dim3(4096, 8), 256, 0, s1>>>(bias);
    cudaEventRecord(eJoin, s1);

    // main stream: pre-round inputs, then QKV GEMM
    hp_cvt4<<<BB*NN*DD/4/256, 256>>>((const float4*)x,    (float4*)gx);
    hp_cvt4<<<DD*3*DD/4/256, 256>>>((const float4*)Wqkv, (float4*)gwq);
    hp_cvt4<<<DD*DD/4/256,   256>>>((const float4*)Wo,   (float4*)gwo);
    hp_gemm_mma<1536, true ><<<dim3(12, 64), 256, gemm_smem>>>(gx, gwq, bqkv, nullptr);

    // join: attention needs both the QKV outputs and the transposed bias
    cudaStreamWaitEvent(0, eJoin, 0);
    hp_attn_mma<<<dim3(HH, NN / 128, BB), 256, attn_smem>>>();
    hp_gemm_mma<512, false><<<dim3(4, 64), 256, gemm_smem>>>(gy, gwo, bo, out);

    cudaEventDestroy(eFork);
    cudaEventDestroy(eJoin);
    cudaStreamDestroy(s1);
}

// round 8
// speedup vs baseline: 3.2402x; 1.0234x over previous
#include <cuda_runtime.h>
#include <math.h>
#include <stdint.h>

#define BB 8
#define NN 1024
#define DD 512
#define HH 8
#define HD 64

__device__ float g_qT[BB*HH*HD*NN];    // [B,H,d,n]   16MB (tf32-rounded)
__device__ float g_kT[BB*HH*HD*NN];    // [B,H,d,n]   16MB (tf32-rounded)
__device__ float g_v [BB*HH*NN*HD];    // [B,H,n,d]   16MB (tf32-rounded)
__device__ float g_y [BB*NN*DD];       // [token, D]  16MB (tf32-rounded)
__device__ float g_x [BB*NN*DD];       // pre-rounded x      16MB
__device__ float g_wq[DD*3*DD];        // pre-rounded W_qkv   3MB
__device__ float g_wo[DD*DD];          // pre-rounded W_o     1MB
__device__ float g_biasT[(size_t)BB*HH*NN*NN];  // [B,H,q,k] 268MB

__device__ __forceinline__ float cvt_tf32(float x) {
    uint32_t u;
    asm("cvt.rna.tf32.f32 %0, %1;" : "=r"(u) : "f"(x));
    return __uint_as_float(u);
}

#define MMA16N8K8(d, a0, a1, a2, a3, b0, b1)                              \
    asm volatile("mma.sync.aligned.m16n8k8.row.col.f32.tf32.tf32.f32 "    \
                 "{%0,%1,%2,%3},{%4,%5,%6,%7},{%8,%9},{%0,%1,%2,%3};"     \
                 : "+f"(d[0]), "+f"(d[1]), "+f"(d[2]), "+f"(d[3])         \
                 : "r"(a0), "r"(a1), "r"(a2), "r"(a3), "r"(b0), "r"(b1))

#define CP16(dst, src) \
    asm volatile("cp.async.cg.shared.global [%0], [%1], 16;" :: "r"(dst), "l"(src))
#define CP_COMMIT() asm volatile("cp.async.commit_group;")
#define CP_WAIT1()  asm volatile("cp.async.wait_group 1;")
#define CP_WAIT0()  asm volatile("cp.async.wait_group 0;")

// ---------------------------------------------------------------------------
// K-pre: elementwise tf32 rounding (float4 vectorized)
// ---------------------------------------------------------------------------
__global__ __launch_bounds__(256) void hp_cvt4(const float4* __restrict__ in,
                                               float4* __restrict__ out)
{
    const size_t i = (size_t)blockIdx.x * 256 + threadIdx.x;
    float4 t = in[i];
    t.x = cvt_tf32(t.x); t.y = cvt_tf32(t.y);
    t.z = cvt_tf32(t.z); t.w = cvt_tf32(t.w);
    out[i] = t;
}

// ---------------------------------------------------------------------------
// K0: bias transpose  [B][q][k][H] -> g_biasT [B][H][q*k]
// PERSISTENT grid-stride form (592 CTAs): leaves SM thread/smem headroom so
// the QKV GEMM co-schedules on the same SMs (true overlap under the graph).
// ---------------------------------------------------------------------------
__global__ __launch_bounds__(256) void hp_bias_T(const float* __restrict__ bias)
{
    const size_t total  = (size_t)BB * 1048576;   // 8M qk-slots (b major)
    const size_t stride = (size_t)gridDim.x * 256;
    for (size_t idx = (size_t)blockIdx.x * 256 + threadIdx.x;
         idx < total; idx += stride) {
        const int    b  = (int)(idx >> 20);
        const size_t qk = idx & 1048575;
        const float4* p = (const float4*)(bias + (idx << 3));
        float4 t0 = p[0];
        float4 t1 = p[1];
        float* o = g_biasT + (size_t)b * 8388608 + qk;
        o[0 * 1048576] = t0.x; o[1 * 1048576] = t0.y;
        o[2 * 1048576] = t0.z; o[3 * 1048576] = t0.w;
        o[4 * 1048576] = t1.x; o[5 * 1048576] = t1.y;
        o[6 * 1048576] = t1.z; o[7 * 1048576] = t1.w;
    }
}

// ---------------------------------------------------------------------------
// K1/K3: tf32 HMMA GEMM, BM=128, BN=128, BK=32, cp.async double-buffered.
// Inputs pre-rounded to tf32 -> inner loop is pure LDS+MMA (no CVT).
// ---------------------------------------------------------------------------
template<int LDN, bool SPLIT>
__global__ __launch_bounds__(256, 2) void hp_gemm_mma(
    const float* __restrict__ A, const float* __restrict__ Wm,
    const float* __restrict__ bv, float* __restrict__ outp)
{
    extern __shared__ float sm[];
    float* As = sm;                 // [2][128*36]
    float* Bs = sm + 2 * 128 * 36;  // [2][32*136]

    const int tid  = threadIdx.x;
    const int warp = tid >> 5, lane = tid & 31;
    const int grp  = lane >> 2, tg = lane & 3;
    const int wm   = warp >> 1, wn = warp & 1;
    const int bm   = blockIdx.y * 128, bn = blockIdx.x * 128;

    const uint32_t sA = (uint32_t)__cvta_generic_to_shared(As);
    const uint32_t sB = (uint32_t)__cvta_generic_to_shared(Bs);

    float acc[2][8][4];
#pragma unroll
    for (int i = 0; i < 2; ++i)
#pragma unroll
        for (int j = 0; j < 8; ++j)
#pragma unroll
            for (int r = 0; r < 4; ++r) acc[i][j][r] = 0.f;

    auto load_tile = [&](int k0, int buf) {
#pragma unroll
        for (int i = 0; i < 4; ++i) {
            int v = i * 256 + tid;
            int r = v >> 3, c4 = (v & 7) << 2;
            CP16(sA + (buf * 128 * 36 + r * 36 + c4) * 4,
                 &A[(size_t)(bm + r) * 512 + k0 + c4]);
        }
#pragma unroll
        for (int i = 0; i < 4; ++i) {
            int v = i * 256 + tid;
            int r = v >> 5, c4 = (v & 31) << 2;
            CP16(sB + (buf * 32 * 136 + r * 136 + c4) * 4,
                 &Wm[(size_t)(k0 + r) * LDN + bn + c4]);
        }
    };

    load_tile(0, 0);
    CP_COMMIT();

    for (int it = 0; it < 16; ++it) {
        const int cur = it & 1;
        if (it < 15) {
            load_tile((it + 1) * 32, cur ^ 1);
            CP_COMMIT();
            CP_WAIT1();
        } else {
            CP_WAIT0();
        }
        __syncthreads();

        const float* Ac = As + cur * 128 * 36;
        const float* Bc = Bs + cur * 32 * 136;
#pragma unroll
        for (int ks = 0; ks < 4; ++ks) {
            const int kb = ks * 8;
            uint32_t a[2][4];
#pragma unroll
            for (int mf = 0; mf < 2; ++mf) {
                int r = wm * 32 + mf * 16 + grp;
                a[mf][0] = __float_as_uint(Ac[r * 36 + kb + tg]);
                a[mf][1] = __float_as_uint(Ac[(r + 8) * 36 + kb + tg]);
                a[mf][2] = __float_as_uint(Ac[r * 36 + kb + tg + 4]);
                a[mf][3] = __float_as_uint(Ac[(r + 8) * 36 + kb + tg + 4]);
            }
#pragma unroll
            for (int nf = 0; nf < 8; ++nf) {
                int c = wn * 64 + nf * 8 + grp;
                uint32_t b0 = __float_as_uint(Bc[(kb + tg) * 136 + c]);
                uint32_t b1 = __float_as_uint(Bc[(kb + tg + 4) * 136 + c]);
                MMA16N8K8(acc[0][nf], a[0][0], a[0][1], a[0][2], a[0][3], b0, b1);
                MMA16N8K8(acc[1][nf], a[1][0], a[1][1], a[1][2], a[1][3], b0, b1);
            }
        }
        __syncthreads();
    }

#pragma unroll
    for (int mf = 0; mf < 2; ++mf) {
#pragma unroll
        for (int rr = 0; rr < 2; ++rr) {
            const int m = bm + wm * 32 + mf * 16 + grp + rr * 8;
#pragma unroll
            for (int nf = 0; nf < 8; ++nf) {
                const int c = bn + wn * 64 + nf * 8 + tg * 2;
                float v0 = acc[mf][nf][rr * 2]     + bv[c];
                float v1 = acc[mf][nf][rr * 2 + 1] + bv[c + 1];
                if (SPLIT) {
                    v0 = cvt_tf32(v0);
                    v1 = cvt_tf32(v1);
                    int bi = m >> 10, n = m & 1023;
                    int h = c / 192, rem = c - h * 192;
                    int which = rem >> 6, t = rem & 63;
                    if (which == 0) {
                        g_qT[(((size_t)bi * 8 + h) * 64 + t)     * 1024 + n] = v0;
                        g_qT[(((size_t)bi * 8 + h) * 64 + t + 1) * 1024 + n] = v1;
                    } else if (which == 1) {
                        g_kT[(((size_t)bi * 8 + h) * 64 + t)     * 1024 + n] = v0;
                        g_kT[(((size_t)bi * 8 + h) * 64 + t + 1) * 1024 + n] = v1;
                    } else {
                        float2 w2 = make_float2(v0, v1);
                        *(float2*)&g_v[(((size_t)bi * 8 + h) * 1024 + n) * 64 + t] = w2;
                    }
                } else {
                    float2 w2 = make_float2(v0, v1);
                    *(float2*)&outp[(size_t)m * 512 + c] = w2;
                }
            }
        }
    }
}

// ---------------------------------------------------------------------------
// K2: flash attention, tf32 HMMA, cp.async double-buffered K/V/bias tiles.
// ---------------------------------------------------------------------------
__global__ __launch_bounds__(256, 2) void hp_attn_mma()
{
    extern __shared__ float sm[];
    float* Ks = sm;                      // 2*64*40  = 5120
    float* Vs = sm + 5120;               // 2*32*72  = 4608
    float* Bb = sm + 9728;               // 2*128*40 = 10240
    float* Ps = sm + 19968;              // 128*36   = 4608

    const int tid  = threadIdx.x;
    const int warp = tid >> 5, lane = tid & 31;
    const int grp  = lane >> 2, tg = lane & 3;
    const int h  = blockIdx.x;
    const int qt = blockIdx.y;
    const int b  = blockIdx.z;
    const int bh = b * HH + h;
    const int q0 = qt * 128;

    const uint32_t sK = (uint32_t)__cvta_generic_to_shared(Ks);
    const uint32_t sV = (uint32_t)__cvta_generic_to_shared(Vs);
    const uint32_t sBb = (uint32_t)__cvta_generic_to_shared(Bb);

    const float* kb = g_kT + (size_t)bh * HD * NN;
    const float* vb = g_v  + (size_t)bh * NN * HD;
    const float* bias_bh = g_biasT + ((size_t)bh << 20);

    auto load_tile = [&](int k0, int buf) {
#pragma unroll
        for (int i = 0; i < 2; ++i) {                 // Ks: 64 x 32
            int v = i * 256 + tid;
            int d = v >> 3, c4 = (v & 7) << 2;
            CP16(sK + (buf * 2560 + d * 40 + c4) * 4,
                 &kb[(size_t)d * NN + k0 + c4]);
        }
#pragma unroll
        for (int i = 0; i < 2; ++i) {                 // Vs: 32 x 64
            int v = i * 256 + tid;
            int r = v >> 4, c4 = (v & 15) << 2;
            CP16(sV + (buf * 2304 + r * 72 + c4) * 4,
                 &vb[(size_t)(k0 + r) * HD + c4]);
        }
#pragma unroll
        for (int i = 0; i < 4; ++i) {                 // Bb: 128 x 32
            int v = i * 256 + tid;
            int r = v >> 3, c4 = (v & 7) << 2;
            CP16(sBb + (buf * 5120 + r * 40 + c4) * 4,
                 &bias_bh[(size_t)(q0 + r) * 1024 + k0 + c4]);
        }
    };

    load_tile(0, 0);
    CP_COMMIT();

    const float* qbase = g_qT + (size_t)bh * HD * NN;
    const int qr = q0 + warp * 16 + grp;
    uint32_t qa[8][4];
#pragma unroll
    for (int s = 0; s < 8; ++s) {
        int d0 = s * 8 + tg;
        qa[s][0] = __float_as_uint(qbase[(size_t)d0       * NN + qr]     * 0.125f);
        qa[s][1] = __float_as_uint(qbase[(size_t)d0       * NN + qr + 8] * 0.125f);
        qa[s][2] = __float_as_uint(qbase[(size_t)(d0 + 4) * NN + qr]     * 0.125f);
        qa[s][3] = __float_as_uint(qbase[(size_t)(d0 + 4) * NN + qr + 8] * 0.125f);
    }

    float o[8][4];
#pragma unroll
    for (int i = 0; i < 8; ++i)
#pragma unroll
        for (int j = 0; j < 4; ++j) o[i][j] = 0.f;
    float m0 = -1e30f, m1 = -1e30f, l0 = 0.f, l1 = 0.f;

    const int r0 = warp * 16 + grp;

    for (int kt = 0; kt < 32; ++kt) {
        const int cur = kt & 1;
        if (kt < 31) {
            load_tile((kt + 1) * 32, cur ^ 1);
            CP_COMMIT();
            CP_WAIT1();
        } else {
            CP_WAIT0();
        }
        __syncthreads();

        const float* Kc = Ks + cur * 2560;
        const float* Vc = Vs + cur * 2304;
        const float* Bc = Bb + cur * 5120;

        float s_[4][4];
#pragma unroll
        for (int nf = 0; nf < 4; ++nf)
#pragma unroll
            for (int r = 0; r < 4; ++r) s_[nf][r] = 0.f;
#pragma unroll
        for (int ks = 0; ks < 8; ++ks) {
#pragma unroll
            for (int nf = 0; nf < 4; ++nf) {
                int key = nf * 8 + grp;
                uint32_t b0 = __float_as_uint(Kc[(ks * 8 + tg) * 40 + key]);
                uint32_t b1 = __float_as_uint(Kc[(ks * 8 + tg + 4) * 40 + key]);
                MMA16N8K8(s_[nf], qa[ks][0], qa[ks][1], qa[ks][2], qa[ks][3], b0, b1);
            }
        }
#pragma unroll
        for (int nf = 0; nf < 4; ++nf) {
            int c = nf * 8 + tg * 2;
            float2 t0 = *(const float2*)&Bc[r0 * 40 + c];
            float2 t1 = *(const float2*)&Bc[(r0 + 8) * 40 + c];
            s_[nf][0] += t0.x; s_[nf][1] += t0.y;
            s_[nf][2] += t1.x; s_[nf][3] += t1.y;
        }

        float mx0 = -1e30f, mx1 = -1e30f;
#pragma unroll
        for (int nf = 0; nf < 4; ++nf) {
            mx0 = fmaxf(mx0, fmaxf(s_[nf][0], s_[nf][1]));
            mx1 = fmaxf(mx1, fmaxf(s_[nf][2], s_[nf][3]));
        }
        mx0 = fmaxf(mx0, __shfl_xor_sync(0xffffffffu, mx0, 1));
        mx0 = fmaxf(mx0, __shfl_xor_sync(0xffffffffu, mx0, 2));
        mx1 = fmaxf(mx1, __shfl_xor_sync(0xffffffffu, mx1, 1));
        mx1 = fmaxf(mx1, __shfl_xor_sync(0xffffffffu, mx1, 2));
        float mn0 = fmaxf(m0, mx0), mn1 = fmaxf(m1, mx1);
        float sc0 = __expf(m0 - mn0), sc1 = __expf(m1 - mn1);
        float sum0 = 0.f, sum1 = 0.f;
#pragma unroll
        for (int nf = 0; nf < 4; ++nf) {
            s_[nf][0] = __expf(s_[nf][0] - mn0);
            s_[nf][1] = __expf(s_[nf][1] - mn0);
            s_[nf][2] = __expf(s_[nf][2] - mn1);
            s_[nf][3] = __expf(s_[nf][3] - mn1);
            sum0 += s_[nf][0] + s_[nf][1];
            sum1 += s_[nf][2] + s_[nf][3];
        }
        sum0 += __shfl_xor_sync(0xffffffffu, sum0, 1);
        sum0 += __shfl_xor_sync(0xffffffffu, sum0, 2);
        sum1 += __shfl_xor_sync(0xffffffffu, sum1, 1);
        sum1 += __shfl_xor_sync(0xffffffffu, sum1, 2);
        l0 = l0 * sc0 + sum0;
        l1 = l1 * sc1 + sum1;
        m0 = mn0; m1 = mn1;

#pragma unroll
        for (int nf = 0; nf < 8; ++nf) {
            o[nf][0] *= sc0; o[nf][1] *= sc0;
            o[nf][2] *= sc1; o[nf][3] *= sc1;
        }

#pragma unroll
        for (int nf = 0; nf < 4; ++nf) {
            int c = nf * 8 + tg * 2;
            float2 p0 = make_float2(cvt_tf32(s_[nf][0]), cvt_tf32(s_[nf][1]));
            float2 p1 = make_float2(cvt_tf32(s_[nf][2]), cvt_tf32(s_[nf][3]));
            *(float2*)&Ps[r0 * 36 + c]       = p0;
            *(float2*)&Ps[(r0 + 8) * 36 + c] = p1;
        }
        __syncwarp();

#pragma unroll
        for (int ks = 0; ks < 4; ++ks) {
            uint32_t a0 = __float_as_uint(Ps[r0 * 36 + ks * 8 + tg]);
            uint32_t a1 = __float_as_uint(Ps[(r0 + 8) * 36 + ks * 8 + tg]);
            uint32_t a2 = __float_as_uint(Ps[r0 * 36 + ks * 8 + tg + 4]);
            uint32_t a3 = __float_as_uint(Ps[(r0 + 8) * 36 + ks * 8 + tg + 4]);
#pragma unroll
            for (int nf = 0; nf < 8; ++nf) {
                int dc = nf * 8 + grp;
                uint32_t b0 = __float_as_uint(Vc[(ks * 8 + tg) * 72 + dc]);
                uint32_t b1 = __float_as_uint(Vc[(ks * 8 + tg + 4) * 72 + dc]);
                MMA16N8K8(o[nf], a0, a1, a2, a3, b0, b1);
            }
        }
        __syncthreads();
    }

    const float inv0 = 1.f / l0, inv1 = 1.f / l1;
    const size_t row0 = (size_t)b * NN + q0 + warp * 16 + grp;
    const size_t row1 = row0 + 8;
#pragma unroll
    for (int nf = 0; nf < 8; ++nf) {
        int c = h * 64 + nf * 8 + tg * 2;
        float2 w0 = make_float2(cvt_tf32(o[nf][0] * inv0), cvt_tf32(o[nf][1] * inv0));
        float2 w1 = make_float2(cvt_tf32(o[nf][2] * inv1), cvt_tf32(o[nf][3] * inv1));
        *(float2*)&g_y[row0 * DD + c] = w0;
        *(float2*)&g_y[row1 * DD + c] = w1;
    }
}

// ---------------------------------------------------------------------------
extern "C" void kernel_launch(void* const* d_in, const int* in_sizes, int n_in,
                              void* d_out, int out_size)
{
    const float* x    = (const float*)d_in[0];
    const float* bias = (const float*)d_in[1];
    const float* Wqkv = (const float*)d_in[2];
    const float* bqkv = (const float*)d_in[3];
    const float* Wo   = (const float*)d_in[4];
    const float* bo   = (const float*)d_in[5];
    float* out = (float*)d_out;

    const int gemm_smem = (2 * 128 * 36 + 2 * 32 * 136) * 4;  // 71680
    const int attn_smem = 24576 * 4;                          // 98304

    cudaFuncSetAttribute(hp_gemm_mma<1536, true>,
                         cudaFuncAttributeMaxDynamicSharedMemorySize, gemm_smem);
    cudaFuncSetAttribute(hp_gemm_mma<512, false>,
                         cudaFuncAttributeMaxDynamicSharedMemorySize, gemm_smem);
    cudaFuncSetAttribute(hp_attn_mma,
                         cudaFuncAttributeMaxDynamicSharedMemorySize, attn_smem);

    float* gx;  cudaGetSymbolAddress((void**)&gx,  g_x);
    float* gwq; cudaGetSymbolAddress((void**)&gwq, g_wq);
    float* gwo; cudaGetSymbolAddress((void**)&gwo, g_wo);
    float* gy;  cudaGetSymbolAddress((void**)&gy,  g_y);

    // Fork: persistent bias transpose (592 CTAs, DRAM-bound, 0 smem) runs on a
    // side stream and CO-RESIDES with the cvt preludes + QKV GEMM (smem-bound).
    cudaStream_t s1;
    cudaStreamCreateWithFlags(&s1, cudaStreamNonBlocking);
    cudaEvent_t eFork, eJoin;
    cudaEventCreateWithFlags(&eFork, cudaEventDisableTiming);
    cudaEventCreateWithFlags(&eJoin, cudaEventDisableTiming);

    cudaEventRecord(eFork, 0);
    cudaStreamWaitEvent(s1, eFork, 0);
    hp_bias_T<<<592, 256, 0, s1>>>(bias);
    cudaEventRecord(eJoin, s1);

    // main stream: pre-round inputs, then QKV GEMM (co-resident with bias_T)
    hp_cvt4<<<BB*NN*DD/4/256, 256>>>((const float4*)x,    (float4*)gx);
    hp_cvt4<<<DD*3*DD/4/256, 256>>>((const float4*)Wqkv, (float4*)gwq);
    hp_cvt4<<<DD*DD/4/256,   256>>>((const float4*)Wo,   (float4*)gwo);
    hp_gemm_mma<1536, true ><<<dim3(12, 64), 256, gemm_smem>>>(gx, gwq, bqkv, nullptr);

    // join: attention needs both the QKV outputs and the transposed bias
    cudaStreamWaitEvent(0, eJoin, 0);
    hp_attn_mma<<<dim3(HH, NN / 128, BB), 256, attn_smem>>>();
    hp_gemm_mma<512, false><<<dim3(4, 64), 256, gemm_smem>>>(gy, gwo, bo, out);

    cudaEventDestroy(eFork);
    cudaEventDestroy(eJoin);
    cudaStreamDestroy(s1);
}